// round 1
// baseline (speedup 1.0000x reference)
#include <cuda_runtime.h>
#include <math.h>

#define NN 32768
#define NE 524288
#define HD 128

__device__ __forceinline__ float ssilu(float v) {
    // silu(x) / 0.6
    return v / ((1.0f + __expf(-v)) * 0.6f);
}

static __device__ float g_xln[NN * HD];
static __device__ float g_t1[NN * HD];
static __device__ float g_xh[NN * 3 * HD];
static __device__ float g_rbfh[(size_t)NE * 3 * HD];
static __device__ float g_dx[NN * HD];
static __device__ float g_dvec[NN * 3 * HD];
static __device__ float g_xnew[NN * HD];
static __device__ float g_vecnew[NN * 3 * HD];
static __device__ float g_vproj[NN * 3 * 2 * HD];
static __device__ float g_vecdot[NN * HD];
static __device__ float g_cat[NN * 2 * HD];
static __device__ float g_u[NN * HD];
static __device__ float g_hbuf[NN * 3 * HD];
static __device__ float g_zerobias[512];   // zero-initialized

__constant__ float C_INV_SQRT_3 = 0.57735026918962576451f;
__constant__ float C_INV_SQRT_H = 0.08838834764831844055f;  // 1/sqrt(128)
__constant__ float C_INV_SQRT_2 = 0.70710678118654752440f;

// ---------------------------------------------------------------------------
// zero accumulators
// ---------------------------------------------------------------------------
__global__ void zero_acc_kernel() {
    int total4 = (NN * HD + NN * 3 * HD) / 4;   // dx + dvec in float4 units
    float4 z = make_float4(0.f, 0.f, 0.f, 0.f);
    for (int i = blockIdx.x * blockDim.x + threadIdx.x; i < total4;
         i += gridDim.x * blockDim.x) {
        if (i < NN * HD / 4)
            ((float4*)g_dx)[i] = z;
        else
            ((float4*)g_dvec)[i - NN * HD / 4] = z;
    }
}

// ---------------------------------------------------------------------------
// LayerNorm: one warp per row of 128
// ---------------------------------------------------------------------------
__global__ void ln_kernel(const float* __restrict__ x,
                          const float* __restrict__ g,
                          const float* __restrict__ b) {
    int row = blockIdx.x * (blockDim.x >> 5) + (threadIdx.x >> 5);
    int lane = threadIdx.x & 31;
    if (row >= NN) return;
    float4 v = *(const float4*)(x + (size_t)row * HD + lane * 4);
    float s = v.x + v.y + v.z + v.w;
    float s2 = v.x * v.x + v.y * v.y + v.z * v.z + v.w * v.w;
#pragma unroll
    for (int o = 16; o > 0; o >>= 1) {
        s += __shfl_xor_sync(0xffffffffu, s, o);
        s2 += __shfl_xor_sync(0xffffffffu, s2, o);
    }
    float mu = s * (1.0f / HD);
    float var = s2 * (1.0f / HD) - mu * mu;
    float inv = rsqrtf(var + 1e-5f);
    float4 gg = *(const float4*)(g + lane * 4);
    float4 bb = *(const float4*)(b + lane * 4);
    float4 o4;
    o4.x = (v.x - mu) * inv * gg.x + bb.x;
    o4.y = (v.y - mu) * inv * gg.y + bb.y;
    o4.z = (v.z - mu) * inv * gg.z + bb.z;
    o4.w = (v.w - mu) * inv * gg.w + bb.w;
    *(float4*)(g_xln + (size_t)row * HD + lane * 4) = o4;
}

// ---------------------------------------------------------------------------
// SGEMM: C[M,N] = act(A[M,K] @ B[K,N] + bias[N])
// BM=BN=128, BK=16, 256 threads, 8x8 per thread (4+4 split). M%128==0,
// N%128==0, K%16==0 for all call sites.
// ---------------------------------------------------------------------------
template <int ACT>
__global__ void gemm128(const float* __restrict__ A, const float* __restrict__ B,
                        const float* __restrict__ bias, float* __restrict__ C,
                        int M, int N, int K) {
    __shared__ float As[16][132];
    __shared__ float Bs[16][128];
    int tid = threadIdx.x;
    int tx = tid & 15;
    int ty = tid >> 4;
    int bm = blockIdx.y * 128;
    int bn = blockIdx.x * 128;

    float acc[8][8];
#pragma unroll
    for (int i = 0; i < 8; i++)
#pragma unroll
        for (int j = 0; j < 8; j++) acc[i][j] = 0.f;

    for (int k0 = 0; k0 < K; k0 += 16) {
#pragma unroll
        for (int i = 0; i < 2; i++) {
            int f = tid + i * 256;          // 512 float4 covering 128x16 A tile
            int row = f >> 2;
            int c4 = (f & 3) * 4;
            float4 v = *(const float4*)(A + (size_t)(bm + row) * K + k0 + c4);
            As[c4 + 0][row] = v.x;
            As[c4 + 1][row] = v.y;
            As[c4 + 2][row] = v.z;
            As[c4 + 3][row] = v.w;
        }
#pragma unroll
        for (int i = 0; i < 2; i++) {
            int f = tid + i * 256;          // 512 float4 covering 16x128 B tile
            int row = f >> 5;
            int c4 = (f & 31) * 4;
            float4 v = *(const float4*)(B + (size_t)(k0 + row) * N + bn + c4);
            *(float4*)(&Bs[row][c4]) = v;
        }
        __syncthreads();
#pragma unroll
        for (int k = 0; k < 16; k++) {
            float a[8], bv[8];
            float4 a0 = *(const float4*)(&As[k][ty * 4]);
            float4 a1 = *(const float4*)(&As[k][64 + ty * 4]);
            float4 b0 = *(const float4*)(&Bs[k][tx * 4]);
            float4 b1 = *(const float4*)(&Bs[k][64 + tx * 4]);
            a[0] = a0.x; a[1] = a0.y; a[2] = a0.z; a[3] = a0.w;
            a[4] = a1.x; a[5] = a1.y; a[6] = a1.z; a[7] = a1.w;
            bv[0] = b0.x; bv[1] = b0.y; bv[2] = b0.z; bv[3] = b0.w;
            bv[4] = b1.x; bv[5] = b1.y; bv[6] = b1.z; bv[7] = b1.w;
#pragma unroll
            for (int i = 0; i < 8; i++)
#pragma unroll
                for (int j = 0; j < 8; j++) acc[i][j] += a[i] * bv[j];
        }
        __syncthreads();
    }

#pragma unroll
    for (int ih = 0; ih < 2; ih++) {
#pragma unroll
        for (int i = 0; i < 4; i++) {
            int row = bm + ih * 64 + ty * 4 + i;
#pragma unroll
            for (int jh = 0; jh < 2; jh++) {
                int col = bn + jh * 64 + tx * 4;
                float4 bb = *(const float4*)(bias + col);
                float4 v;
                v.x = acc[ih * 4 + i][jh * 4 + 0] + bb.x;
                v.y = acc[ih * 4 + i][jh * 4 + 1] + bb.y;
                v.z = acc[ih * 4 + i][jh * 4 + 2] + bb.z;
                v.w = acc[ih * 4 + i][jh * 4 + 3] + bb.w;
                if (ACT) {
                    v.x = ssilu(v.x);
                    v.y = ssilu(v.y);
                    v.z = ssilu(v.z);
                    v.w = ssilu(v.w);
                }
                *(float4*)(C + (size_t)row * N + col) = v;
            }
        }
    }
}

// ---------------------------------------------------------------------------
// Edge message kernel: one warp per edge, vectorized f32x4 reductions.
// ---------------------------------------------------------------------------
__device__ __forceinline__ void red4(float* addr, float4 v) {
    asm volatile("red.global.add.v4.f32 [%0], {%1, %2, %3, %4};"
                 :: "l"(addr), "f"(v.x), "f"(v.y), "f"(v.z), "f"(v.w)
                 : "memory");
}

__global__ void edge_msg_kernel(const int* __restrict__ ei,
                                const float* __restrict__ vec,
                                const float* __restrict__ edge_vec) {
    int e = (blockIdx.x * blockDim.x + threadIdx.x) >> 5;
    if (e >= NE) return;
    int lane = threadIdx.x & 31;
    int src = ei[e];
    int dst = ei[NE + e];
    float ev[3];
    ev[0] = edge_vec[(size_t)e * 3 + 0];
    ev[1] = edge_vec[(size_t)e * 3 + 1];
    ev[2] = edge_vec[(size_t)e * 3 + 2];

    const float4* xh4 = (const float4*)(g_xh + (size_t)src * 384);
    const float4* rb4 = (const float4*)(g_rbfh + (size_t)e * 384);
    float4 a1 = xh4[lane],      r1 = rb4[lane];
    float4 a2 = xh4[32 + lane], r2 = rb4[32 + lane];
    float4 a3 = xh4[64 + lane], r3 = rb4[64 + lane];

    float4 m1, m2, m3;
    m1.x = a1.x * r1.x; m1.y = a1.y * r1.y; m1.z = a1.z * r1.z; m1.w = a1.w * r1.w;
    m2.x = a2.x * r2.x * C_INV_SQRT_3; m2.y = a2.y * r2.y * C_INV_SQRT_3;
    m2.z = a2.z * r2.z * C_INV_SQRT_3; m2.w = a2.w * r2.w * C_INV_SQRT_3;
    m3.x = a3.x * r3.x; m3.y = a3.y * r3.y; m3.z = a3.z * r3.z; m3.w = a3.w * r3.w;

    red4(g_dx + (size_t)dst * HD + lane * 4, m1);

    const float4* vv4 = (const float4*)(vec + (size_t)src * 384);
#pragma unroll
    for (int c = 0; c < 3; c++) {
        float4 vv = vv4[c * 32 + lane];
        float4 msg;
        msg.x = (vv.x * m2.x + m3.x * ev[c]) * C_INV_SQRT_H;
        msg.y = (vv.y * m2.y + m3.y * ev[c]) * C_INV_SQRT_H;
        msg.z = (vv.z * m2.z + m3.z * ev[c]) * C_INV_SQRT_H;
        msg.w = (vv.w * m2.w + m3.w * ev[c]) * C_INV_SQRT_H;
        red4(g_dvec + (size_t)dst * 384 + c * HD + lane * 4, msg);
    }
}

// ---------------------------------------------------------------------------
// x_new = (x + dx)/sqrt(2);  vec_new = vec + dvec
// ---------------------------------------------------------------------------
__global__ void node_mid_kernel(const float* __restrict__ x,
                                const float* __restrict__ vec) {
    int i = blockIdx.x * blockDim.x + threadIdx.x;
    if (i < NN * 3 * HD) g_vecnew[i] = vec[i] + g_dvec[i];
    if (i < NN * HD) g_xnew[i] = (x[i] + g_dx[i]) * C_INV_SQRT_2;
}

// ---------------------------------------------------------------------------
// vec_dot, vec2_norm, cat([x_new, vnorm])
// ---------------------------------------------------------------------------
__global__ void dotnorm_kernel() {
    int i = blockIdx.x * blockDim.x + threadIdx.x;
    if (i >= NN * HD) return;
    int n = i >> 7;
    int h = i & 127;
    const float* vp = g_vproj + (size_t)n * 768;
    float d = 0.f, s = 0.f;
#pragma unroll
    for (int c = 0; c < 3; c++) {
        float v1 = vp[c * 256 + h];
        float v2 = vp[c * 256 + 128 + h];
        d += v1 * v2;
        s += v2 * v2;
    }
    g_vecdot[i] = d * C_INV_SQRT_H;
    g_cat[(size_t)n * 256 + h] = g_xnew[i];
    g_cat[(size_t)n * 256 + 128 + h] = sqrtf(s + 1e-8f);
}

// ---------------------------------------------------------------------------
// finalize: out = [vec_out (N,3,H), x_out (N,H)]
// ---------------------------------------------------------------------------
__global__ void finalize_kernel(float* __restrict__ out) {
    int i = blockIdx.x * blockDim.x + threadIdx.x;
    if (i >= NN * HD) return;
    int n = i >> 7;
    int h = i & 127;
    const float* hb = g_hbuf + (size_t)n * 384;
    float xv1 = hb[h];
    float xv2 = hb[128 + h];
    float xv3 = hb[256 + h];
    float* out_vec = out;
    float* out_x = out + (size_t)NN * 3 * HD;
    out_x[i] = g_xnew[i] + (xv1 + xv2 * g_vecdot[i]) * C_INV_SQRT_2;
#pragma unroll
    for (int c = 0; c < 3; c++) {
        size_t idx = (size_t)n * 384 + c * HD + h;
        out_vec[idx] = g_vecnew[idx] + xv3 * g_vproj[(size_t)n * 768 + c * 256 + h];
    }
}

// ---------------------------------------------------------------------------
extern "C" void kernel_launch(void* const* d_in, const int* in_sizes, int n_in,
                              void* d_out, int out_size) {
    const float* x        = (const float*)d_in[0];
    const float* vec      = (const float*)d_in[1];
    const int*   ei       = (const int*)d_in[2];
    const float* ee       = (const float*)d_in[3];
    const float* evec     = (const float*)d_in[4];
    const float* ln_g     = (const float*)d_in[5];
    const float* ln_b     = (const float*)d_in[6];
    const float* W1       = (const float*)d_in[7];
    const float* b1       = (const float*)d_in[8];
    const float* W2       = (const float*)d_in[9];
    const float* b2       = (const float*)d_in[10];
    const float* Wr       = (const float*)d_in[11];
    const float* br       = (const float*)d_in[12];
    const float* Wv       = (const float*)d_in[13];
    const float* Wu1      = (const float*)d_in[14];
    const float* bu1      = (const float*)d_in[15];
    const float* Wu2      = (const float*)d_in[16];
    const float* bu2      = (const float*)d_in[17];

    float* out = (float*)d_out;

    float* zb = nullptr;
    cudaGetSymbolAddress((void**)&zb, g_zerobias);

    float* xln = nullptr;   cudaGetSymbolAddress((void**)&xln, g_xln);
    float* t1 = nullptr;    cudaGetSymbolAddress((void**)&t1, g_t1);
    float* xh = nullptr;    cudaGetSymbolAddress((void**)&xh, g_xh);
    float* rbfh = nullptr;  cudaGetSymbolAddress((void**)&rbfh, g_rbfh);
    float* vecnew = nullptr; cudaGetSymbolAddress((void**)&vecnew, g_vecnew);
    float* vproj = nullptr;  cudaGetSymbolAddress((void**)&vproj, g_vproj);
    float* cat = nullptr;    cudaGetSymbolAddress((void**)&cat, g_cat);
    float* u = nullptr;      cudaGetSymbolAddress((void**)&u, g_u);
    float* hbuf = nullptr;   cudaGetSymbolAddress((void**)&hbuf, g_hbuf);

    // 1. zero dx/dvec accumulators
    zero_acc_kernel<<<4096, 256>>>();

    // 2. LayerNorm
    ln_kernel<<<NN / 8, 256>>>(x, ln_g, ln_b);

    // 3. t1 = scaled_silu(xln @ W1 + b1)   [N,128]
    gemm128<1><<<dim3(1, NN / 128), 256>>>(xln, W1, b1, t1, NN, 128, 128);

    // 4. xh = t1 @ W2 + b2                 [N,384]
    gemm128<0><<<dim3(3, NN / 128), 256>>>(t1, W2, b2, xh, NN, 384, 128);

    // 5. rbfh = edge_embed @ Wr + br       [E,384]
    gemm128<0><<<dim3(3, NE / 128), 256>>>(ee, Wr, br, rbfh, NE, 384, 64);

    // 6. edge messages + scatter (vectorized f32x4 reductions)
    edge_msg_kernel<<<NE / 8, 256>>>(ei, vec, evec);

    // 7. x_new, vec_new
    node_mid_kernel<<<(NN * 3 * HD + 255) / 256, 256>>>(x, vec);

    // 8. vproj = vec_new(3N,128) @ Wv(128,256)
    gemm128<0><<<dim3(2, (3 * NN) / 128), 256>>>(vecnew, Wv, zb, vproj,
                                                 3 * NN, 256, 128);

    // 9. vec_dot / vec2_norm / cat
    dotnorm_kernel<<<(NN * HD) / 256, 256>>>();

    // 10. u = scaled_silu(cat @ Wu1 + bu1)  [N,128]
    gemm128<1><<<dim3(1, NN / 128), 256>>>(cat, Wu1, bu1, u, NN, 128, 256);

    // 11. h = u @ Wu2 + bu2                 [N,384]
    gemm128<0><<<dim3(3, NN / 128), 256>>>(u, Wu2, bu2, hbuf, NN, 384, 128);

    // 12. finalize
    finalize_kernel<<<(NN * HD) / 256, 256>>>(out);
}

// round 2
// speedup vs baseline: 1.0158x; 1.0158x over previous
#include <cuda_runtime.h>
#include <math.h>

#define NN 32768
#define NE 524288
#define HD 128

__device__ __forceinline__ float ssilu(float v) {
    return v / ((1.0f + __expf(-v)) * 0.6f);
}

static __device__ float g_xln[NN * HD];
static __device__ float g_t1[NN * HD];
static __device__ float g_xh[NN * 3 * HD];
static __device__ float g_dx[NN * HD];
static __device__ float g_dvec[NN * 3 * HD];
static __device__ float g_xnew[NN * HD];
static __device__ float g_vecnew[NN * 3 * HD];
static __device__ float g_vproj[NN * 3 * 2 * HD];
static __device__ float g_vecdot[NN * HD];
static __device__ float g_cat[NN * 2 * HD];
static __device__ float g_u[NN * HD];
static __device__ float g_hbuf[NN * 3 * HD];
static __device__ float g_zerobias[512];

__constant__ float C_INV_SQRT_3 = 0.57735026918962576451f;
__constant__ float C_INV_SQRT_H = 0.08838834764831844055f;
__constant__ float C_INV_SQRT_2 = 0.70710678118654752440f;

// ---------------------------------------------------------------------------
__global__ void zero_acc_kernel() {
    int total4 = (NN * HD + NN * 3 * HD) / 4;
    float4 z = make_float4(0.f, 0.f, 0.f, 0.f);
    for (int i = blockIdx.x * blockDim.x + threadIdx.x; i < total4;
         i += gridDim.x * blockDim.x) {
        if (i < NN * HD / 4)
            ((float4*)g_dx)[i] = z;
        else
            ((float4*)g_dvec)[i - NN * HD / 4] = z;
    }
}

// ---------------------------------------------------------------------------
__global__ void ln_kernel(const float* __restrict__ x,
                          const float* __restrict__ g,
                          const float* __restrict__ b) {
    int row = blockIdx.x * (blockDim.x >> 5) + (threadIdx.x >> 5);
    int lane = threadIdx.x & 31;
    if (row >= NN) return;
    float4 v = *(const float4*)(x + (size_t)row * HD + lane * 4);
    float s = v.x + v.y + v.z + v.w;
    float s2 = v.x * v.x + v.y * v.y + v.z * v.z + v.w * v.w;
#pragma unroll
    for (int o = 16; o > 0; o >>= 1) {
        s += __shfl_xor_sync(0xffffffffu, s, o);
        s2 += __shfl_xor_sync(0xffffffffu, s2, o);
    }
    float mu = s * (1.0f / HD);
    float var = s2 * (1.0f / HD) - mu * mu;
    float inv = rsqrtf(var + 1e-5f);
    float4 gg = *(const float4*)(g + lane * 4);
    float4 bb = *(const float4*)(b + lane * 4);
    float4 o4;
    o4.x = (v.x - mu) * inv * gg.x + bb.x;
    o4.y = (v.y - mu) * inv * gg.y + bb.y;
    o4.z = (v.z - mu) * inv * gg.z + bb.z;
    o4.w = (v.w - mu) * inv * gg.w + bb.w;
    *(float4*)(g_xln + (size_t)row * HD + lane * 4) = o4;
}

// ---------------------------------------------------------------------------
// Generic 128x128x16-tiled SGEMM for node layers.
// ---------------------------------------------------------------------------
template <int ACT>
__global__ void gemm128(const float* __restrict__ A, const float* __restrict__ B,
                        const float* __restrict__ bias, float* __restrict__ C,
                        int M, int N, int K) {
    __shared__ float As[16][132];
    __shared__ float Bs[16][128];
    int tid = threadIdx.x;
    int tx = tid & 15;
    int ty = tid >> 4;
    int bm = blockIdx.y * 128;
    int bn = blockIdx.x * 128;

    float acc[8][8];
#pragma unroll
    for (int i = 0; i < 8; i++)
#pragma unroll
        for (int j = 0; j < 8; j++) acc[i][j] = 0.f;

    for (int k0 = 0; k0 < K; k0 += 16) {
#pragma unroll
        for (int i = 0; i < 2; i++) {
            int f = tid + i * 256;
            int row = f >> 2;
            int c4 = (f & 3) * 4;
            float4 v = *(const float4*)(A + (size_t)(bm + row) * K + k0 + c4);
            As[c4 + 0][row] = v.x;
            As[c4 + 1][row] = v.y;
            As[c4 + 2][row] = v.z;
            As[c4 + 3][row] = v.w;
        }
#pragma unroll
        for (int i = 0; i < 2; i++) {
            int f = tid + i * 256;
            int row = f >> 5;
            int c4 = (f & 31) * 4;
            float4 v = *(const float4*)(B + (size_t)(k0 + row) * N + bn + c4);
            *(float4*)(&Bs[row][c4]) = v;
        }
        __syncthreads();
#pragma unroll
        for (int k = 0; k < 16; k++) {
            float a[8], bv[8];
            float4 a0 = *(const float4*)(&As[k][ty * 4]);
            float4 a1 = *(const float4*)(&As[k][64 + ty * 4]);
            float4 b0 = *(const float4*)(&Bs[k][tx * 4]);
            float4 b1 = *(const float4*)(&Bs[k][64 + tx * 4]);
            a[0] = a0.x; a[1] = a0.y; a[2] = a0.z; a[3] = a0.w;
            a[4] = a1.x; a[5] = a1.y; a[6] = a1.z; a[7] = a1.w;
            bv[0] = b0.x; bv[1] = b0.y; bv[2] = b0.z; bv[3] = b0.w;
            bv[4] = b1.x; bv[5] = b1.y; bv[6] = b1.z; bv[7] = b1.w;
#pragma unroll
            for (int i = 0; i < 8; i++)
#pragma unroll
                for (int j = 0; j < 8; j++) acc[i][j] += a[i] * bv[j];
        }
        __syncthreads();
    }

#pragma unroll
    for (int ih = 0; ih < 2; ih++) {
#pragma unroll
        for (int i = 0; i < 4; i++) {
            int row = bm + ih * 64 + ty * 4 + i;
#pragma unroll
            for (int jh = 0; jh < 2; jh++) {
                int col = bn + jh * 64 + tx * 4;
                float4 bb = *(const float4*)(bias + col);
                float4 v;
                v.x = acc[ih * 4 + i][jh * 4 + 0] + bb.x;
                v.y = acc[ih * 4 + i][jh * 4 + 1] + bb.y;
                v.z = acc[ih * 4 + i][jh * 4 + 2] + bb.z;
                v.w = acc[ih * 4 + i][jh * 4 + 3] + bb.w;
                if (ACT) {
                    v.x = ssilu(v.x);
                    v.y = ssilu(v.y);
                    v.z = ssilu(v.z);
                    v.w = ssilu(v.w);
                }
                *(float4*)(C + (size_t)row * N + col) = v;
            }
        }
    }
}

// ---------------------------------------------------------------------------
__device__ __forceinline__ void red4(float* addr, float4 v) {
    asm volatile("red.global.add.v4.f32 [%0], {%1, %2, %3, %4};"
                 :: "l"(addr), "f"(v.x), "f"(v.y), "f"(v.z), "f"(v.w)
                 : "memory");
}

// ---------------------------------------------------------------------------
// Kernel A: fused  dx += xh1[src] * (ee @ Wr[:,0:128] + br[0:128])  scatter.
// 128 edges x 128 cols per block, K=64.
// ---------------------------------------------------------------------------
__global__ void edge_gemm_dx(const float* __restrict__ ee,
                             const float* __restrict__ Wr,
                             const float* __restrict__ br,
                             const int* __restrict__ ei) {
    __shared__ float As[16][132];
    __shared__ float Bs[16][128];
    __shared__ int s_src[128];
    __shared__ int s_dst[128];
    int tid = threadIdx.x;
    int tx = tid & 15;
    int ty = tid >> 4;
    int bm = blockIdx.x * 128;

    if (tid < 128) {
        s_src[tid] = ei[bm + tid];
        s_dst[tid] = ei[NE + bm + tid];
    }

    float acc[8][8];
#pragma unroll
    for (int i = 0; i < 8; i++)
#pragma unroll
        for (int j = 0; j < 8; j++) acc[i][j] = 0.f;

    for (int k0 = 0; k0 < 64; k0 += 16) {
#pragma unroll
        for (int i = 0; i < 2; i++) {
            int f = tid + i * 256;
            int row = f >> 2;
            int c4 = (f & 3) * 4;
            float4 v = *(const float4*)(ee + (size_t)(bm + row) * 64 + k0 + c4);
            As[c4 + 0][row] = v.x;
            As[c4 + 1][row] = v.y;
            As[c4 + 2][row] = v.z;
            As[c4 + 3][row] = v.w;
        }
#pragma unroll
        for (int i = 0; i < 2; i++) {
            int f = tid + i * 256;
            int row = f >> 5;
            int c4 = (f & 31) * 4;
            float4 v = *(const float4*)(Wr + (size_t)(k0 + row) * 384 + c4);
            *(float4*)(&Bs[row][c4]) = v;
        }
        __syncthreads();
#pragma unroll
        for (int k = 0; k < 16; k++) {
            float a[8], bv[8];
            float4 a0 = *(const float4*)(&As[k][ty * 4]);
            float4 a1 = *(const float4*)(&As[k][64 + ty * 4]);
            float4 b0 = *(const float4*)(&Bs[k][tx * 4]);
            float4 b1 = *(const float4*)(&Bs[k][64 + tx * 4]);
            a[0] = a0.x; a[1] = a0.y; a[2] = a0.z; a[3] = a0.w;
            a[4] = a1.x; a[5] = a1.y; a[6] = a1.z; a[7] = a1.w;
            bv[0] = b0.x; bv[1] = b0.y; bv[2] = b0.z; bv[3] = b0.w;
            bv[4] = b1.x; bv[5] = b1.y; bv[6] = b1.z; bv[7] = b1.w;
#pragma unroll
            for (int i = 0; i < 8; i++)
#pragma unroll
                for (int j = 0; j < 8; j++) acc[i][j] += a[i] * bv[j];
        }
        __syncthreads();
    }

#pragma unroll
    for (int ih = 0; ih < 2; ih++) {
#pragma unroll
        for (int i = 0; i < 4; i++) {
            int rl = ih * 64 + ty * 4 + i;
            int src = s_src[rl];
            int dst = s_dst[rl];
            const float* xhp = g_xh + (size_t)src * 384;
#pragma unroll
            for (int jh = 0; jh < 2; jh++) {
                int col = jh * 64 + tx * 4;
                float4 bb = *(const float4*)(br + col);
                float4 x1 = *(const float4*)(xhp + col);
                float4 m;
                m.x = (acc[ih * 4 + i][jh * 4 + 0] + bb.x) * x1.x;
                m.y = (acc[ih * 4 + i][jh * 4 + 1] + bb.y) * x1.y;
                m.z = (acc[ih * 4 + i][jh * 4 + 2] + bb.z) * x1.z;
                m.w = (acc[ih * 4 + i][jh * 4 + 3] + bb.w) * x1.w;
                red4(g_dx + (size_t)dst * HD + col, m);
            }
        }
    }
}

// ---------------------------------------------------------------------------
// Kernel B: fused dvec scatter.
// rbf2 = ee @ Wr[:,128:256] + br[128:256], rbf3 = ee @ Wr[:,256:384] + br[..]
// m2 = xh2[src]*rbf2*inv3 ; m3 = xh3[src]*rbf3
// dvec[dst][c] += (vec[src][c]*m2 + m3*ev[c]) * invH
// 64 edges x 256 cols per block, K=64, 256 threads, 4x16 accs each.
// ---------------------------------------------------------------------------
__global__ void edge_gemm_dvec(const float* __restrict__ ee,
                               const float* __restrict__ Wr,
                               const float* __restrict__ br,
                               const int* __restrict__ ei,
                               const float* __restrict__ vec,
                               const float* __restrict__ evec) {
    __shared__ float As[16][68];
    __shared__ float Bs[16][256];
    __shared__ int s_src[64];
    __shared__ int s_dst[64];
    __shared__ float s_ev[3][64];
    int tid = threadIdx.x;
    int tx = tid & 15;
    int ty = tid >> 4;
    int bm = blockIdx.x * 64;

    if (tid < 64) {
        s_src[tid] = ei[bm + tid];
        s_dst[tid] = ei[NE + bm + tid];
    }
    if (tid < 192) {
        int e = tid & 63;
        int c = tid >> 6;
        s_ev[c][e] = evec[(size_t)(bm + e) * 3 + c];
    }

    float acc[4][16];
#pragma unroll
    for (int i = 0; i < 4; i++)
#pragma unroll
        for (int j = 0; j < 16; j++) acc[i][j] = 0.f;

    for (int k0 = 0; k0 < 64; k0 += 16) {
        {
            int f = tid;                      // 64x16 A tile = 256 float4
            int row = f >> 2;
            int c4 = (f & 3) * 4;
            float4 v = *(const float4*)(ee + (size_t)(bm + row) * 64 + k0 + c4);
            As[c4 + 0][row] = v.x;
            As[c4 + 1][row] = v.y;
            As[c4 + 2][row] = v.z;
            As[c4 + 3][row] = v.w;
        }
#pragma unroll
        for (int i = 0; i < 4; i++) {        // 16x256 B tile = 1024 float4
            int f = tid + i * 256;
            int row = f >> 6;
            int c4 = (f & 63) * 4;
            float4 v = *(const float4*)(Wr + (size_t)(k0 + row) * 384 + 128 + c4);
            *(float4*)(&Bs[row][c4]) = v;
        }
        __syncthreads();
#pragma unroll
        for (int k = 0; k < 16; k++) {
            float4 a = *(const float4*)(&As[k][ty * 4]);
            float av[4] = {a.x, a.y, a.z, a.w};
#pragma unroll
            for (int g = 0; g < 4; g++) {
                float4 b = *(const float4*)(&Bs[k][g * 64 + tx * 4]);
#pragma unroll
                for (int r = 0; r < 4; r++) {
                    acc[r][g * 4 + 0] += av[r] * b.x;
                    acc[r][g * 4 + 1] += av[r] * b.y;
                    acc[r][g * 4 + 2] += av[r] * b.z;
                    acc[r][g * 4 + 3] += av[r] * b.w;
                }
            }
        }
        __syncthreads();
    }

#pragma unroll
    for (int r = 0; r < 4; r++) {
        int rl = ty * 4 + r;
        int src = s_src[rl];
        int dst = s_dst[rl];
        float evv[3] = {s_ev[0][rl], s_ev[1][rl], s_ev[2][rl]};
        const float* xhp = g_xh + (size_t)src * 384;
        const float* vp = vec + (size_t)src * 384;
        float* dvp = g_dvec + (size_t)dst * 384;
#pragma unroll
        for (int g = 0; g < 2; g++) {
            int j = g * 64 + tx * 4;
            float4 b2 = *(const float4*)(br + 128 + j);
            float4 b3 = *(const float4*)(br + 256 + j);
            float4 x2 = *(const float4*)(xhp + 128 + j);
            float4 x3 = *(const float4*)(xhp + 256 + j);
            float4 m2, m3;
            m2.x = (acc[r][g * 4 + 0] + b2.x) * x2.x * C_INV_SQRT_3;
            m2.y = (acc[r][g * 4 + 1] + b2.y) * x2.y * C_INV_SQRT_3;
            m2.z = (acc[r][g * 4 + 2] + b2.z) * x2.z * C_INV_SQRT_3;
            m2.w = (acc[r][g * 4 + 3] + b2.w) * x2.w * C_INV_SQRT_3;
            m3.x = (acc[r][(g + 2) * 4 + 0] + b3.x) * x3.x;
            m3.y = (acc[r][(g + 2) * 4 + 1] + b3.y) * x3.y;
            m3.z = (acc[r][(g + 2) * 4 + 2] + b3.z) * x3.z;
            m3.w = (acc[r][(g + 2) * 4 + 3] + b3.w) * x3.w;
#pragma unroll
            for (int c = 0; c < 3; c++) {
                float4 vv = *(const float4*)(vp + c * 128 + j);
                float ev = evv[c];
                float4 msg;
                msg.x = (vv.x * m2.x + m3.x * ev) * C_INV_SQRT_H;
                msg.y = (vv.y * m2.y + m3.y * ev) * C_INV_SQRT_H;
                msg.z = (vv.z * m2.z + m3.z * ev) * C_INV_SQRT_H;
                msg.w = (vv.w * m2.w + m3.w * ev) * C_INV_SQRT_H;
                red4(dvp + c * 128 + j, msg);
            }
        }
    }
}

// ---------------------------------------------------------------------------
__global__ void node_mid_kernel(const float* __restrict__ x,
                                const float* __restrict__ vec) {
    int i = blockIdx.x * blockDim.x + threadIdx.x;
    if (i < NN * 3 * HD) g_vecnew[i] = vec[i] + g_dvec[i];
    if (i < NN * HD) g_xnew[i] = (x[i] + g_dx[i]) * C_INV_SQRT_2;
}

// ---------------------------------------------------------------------------
__global__ void dotnorm_kernel() {
    int i = blockIdx.x * blockDim.x + threadIdx.x;
    if (i >= NN * HD) return;
    int n = i >> 7;
    int h = i & 127;
    const float* vp = g_vproj + (size_t)n * 768;
    float d = 0.f, s = 0.f;
#pragma unroll
    for (int c = 0; c < 3; c++) {
        float v1 = vp[c * 256 + h];
        float v2 = vp[c * 256 + 128 + h];
        d += v1 * v2;
        s += v2 * v2;
    }
    g_vecdot[i] = d * C_INV_SQRT_H;
    g_cat[(size_t)n * 256 + h] = g_xnew[i];
    g_cat[(size_t)n * 256 + 128 + h] = sqrtf(s + 1e-8f);
}

// ---------------------------------------------------------------------------
__global__ void finalize_kernel(float* __restrict__ out) {
    int i = blockIdx.x * blockDim.x + threadIdx.x;
    if (i >= NN * HD) return;
    int n = i >> 7;
    int h = i & 127;
    const float* hb = g_hbuf + (size_t)n * 384;
    float xv1 = hb[h];
    float xv2 = hb[128 + h];
    float xv3 = hb[256 + h];
    float* out_vec = out;
    float* out_x = out + (size_t)NN * 3 * HD;
    out_x[i] = g_xnew[i] + (xv1 + xv2 * g_vecdot[i]) * C_INV_SQRT_2;
#pragma unroll
    for (int c = 0; c < 3; c++) {
        size_t idx = (size_t)n * 384 + c * HD + h;
        out_vec[idx] = g_vecnew[idx] + xv3 * g_vproj[(size_t)n * 768 + c * 256 + h];
    }
}

// ---------------------------------------------------------------------------
extern "C" void kernel_launch(void* const* d_in, const int* in_sizes, int n_in,
                              void* d_out, int out_size) {
    const float* x    = (const float*)d_in[0];
    const float* vec  = (const float*)d_in[1];
    const int*   ei   = (const int*)d_in[2];
    const float* ee   = (const float*)d_in[3];
    const float* evec = (const float*)d_in[4];
    const float* ln_g = (const float*)d_in[5];
    const float* ln_b = (const float*)d_in[6];
    const float* W1   = (const float*)d_in[7];
    const float* b1   = (const float*)d_in[8];
    const float* W2   = (const float*)d_in[9];
    const float* b2   = (const float*)d_in[10];
    const float* Wr   = (const float*)d_in[11];
    const float* br   = (const float*)d_in[12];
    const float* Wv   = (const float*)d_in[13];
    const float* Wu1  = (const float*)d_in[14];
    const float* bu1  = (const float*)d_in[15];
    const float* Wu2  = (const float*)d_in[16];
    const float* bu2  = (const float*)d_in[17];

    float* out = (float*)d_out;

    float* zb = nullptr;     cudaGetSymbolAddress((void**)&zb, g_zerobias);
    float* xln = nullptr;    cudaGetSymbolAddress((void**)&xln, g_xln);
    float* t1 = nullptr;     cudaGetSymbolAddress((void**)&t1, g_t1);
    float* xh = nullptr;     cudaGetSymbolAddress((void**)&xh, g_xh);
    float* vecnew = nullptr; cudaGetSymbolAddress((void**)&vecnew, g_vecnew);
    float* vproj = nullptr;  cudaGetSymbolAddress((void**)&vproj, g_vproj);
    float* cat = nullptr;    cudaGetSymbolAddress((void**)&cat, g_cat);
    float* u = nullptr;      cudaGetSymbolAddress((void**)&u, g_u);
    float* hbuf = nullptr;   cudaGetSymbolAddress((void**)&hbuf, g_hbuf);

    // 1. zero dx/dvec accumulators
    zero_acc_kernel<<<4096, 256>>>();

    // 2. LayerNorm
    ln_kernel<<<NN / 8, 256>>>(x, ln_g, ln_b);

    // 3. t1 = scaled_silu(xln @ W1 + b1)
    gemm128<1><<<dim3(1, NN / 128), 256>>>(xln, W1, b1, t1, NN, 128, 128);

    // 4. xh = t1 @ W2 + b2
    gemm128<0><<<dim3(3, NN / 128), 256>>>(t1, W2, b2, xh, NN, 384, 128);

    // 5+6. fused rbfh GEMM + edge message + scatter (no rbfh materialization)
    edge_gemm_dx<<<NE / 128, 256>>>(ee, Wr, br, ei);
    edge_gemm_dvec<<<NE / 64, 256>>>(ee, Wr, br, ei, vec, evec);

    // 7. x_new, vec_new
    node_mid_kernel<<<(NN * 3 * HD + 255) / 256, 256>>>(x, vec);

    // 8. vproj = vec_new(3N,128) @ Wv(128,256)
    gemm128<0><<<dim3(2, (3 * NN) / 128), 256>>>(vecnew, Wv, zb, vproj,
                                                 3 * NN, 256, 128);

    // 9. vec_dot / vec2_norm / cat
    dotnorm_kernel<<<(NN * HD) / 256, 256>>>();

    // 10. u = scaled_silu(cat @ Wu1 + bu1)
    gemm128<1><<<dim3(1, NN / 128), 256>>>(cat, Wu1, bu1, u, NN, 128, 256);

    // 11. h = u @ Wu2 + bu2
    gemm128<0><<<dim3(3, NN / 128), 256>>>(u, Wu2, bu2, hbuf, NN, 384, 128);

    // 12. finalize
    finalize_kernel<<<(NN * HD) / 256, 256>>>(out);
}

// round 3
// speedup vs baseline: 1.5680x; 1.5436x over previous
#include <cuda_runtime.h>
#include <math.h>
#include <stdint.h>

#define NN 32768
#define NE 524288
#define HD 128

__device__ __forceinline__ float ssilu(float v) {
    return v / ((1.0f + __expf(-v)) * 0.6f);
}

static __device__ float g_xln[NN * HD];
static __device__ float g_t1[NN * HD];
static __device__ float g_xh[NN * 3 * HD];
static __device__ float g_dx[NN * HD];
static __device__ float g_dvec[NN * 3 * HD];
static __device__ float g_xnew[NN * HD];
static __device__ float g_vecnew[NN * 3 * HD];
static __device__ float g_vproj[NN * 3 * 2 * HD];
static __device__ float g_vecdot[NN * HD];
static __device__ float g_cat[NN * 2 * HD];
static __device__ float g_u[NN * HD];
static __device__ float g_hbuf[NN * 3 * HD];
static __device__ float g_zerobias[512];

__constant__ float C_INV_SQRT_3 = 0.57735026918962576451f;
__constant__ float C_INV_SQRT_H = 0.08838834764831844055f;
__constant__ float C_INV_SQRT_2 = 0.70710678118654752440f;

// ---------------------------------------------------------------------------
__device__ __forceinline__ float f2tf32(float x) {
    float r;
    asm("cvt.rna.tf32.f32 %0, %1;" : "=f"(r) : "f"(x));
    return r;
}

__device__ __forceinline__ void mma8(float c[4], const uint32_t a[4],
                                     uint32_t b0, uint32_t b1) {
    asm volatile(
        "mma.sync.aligned.m16n8k8.row.col.f32.tf32.tf32.f32 "
        "{%0,%1,%2,%3}, {%4,%5,%6,%7}, {%8,%9}, {%0,%1,%2,%3};"
        : "+f"(c[0]), "+f"(c[1]), "+f"(c[2]), "+f"(c[3])
        : "r"(a[0]), "r"(a[1]), "r"(a[2]), "r"(a[3]), "r"(b0), "r"(b1));
}

__device__ __forceinline__ void red2(float* addr, float x, float y) {
    asm volatile("red.global.add.v2.f32 [%0], {%1, %2};"
                 :: "l"(addr), "f"(x), "f"(y) : "memory");
}

__device__ __forceinline__ void red4(float* addr, float4 v) {
    asm volatile("red.global.add.v4.f32 [%0], {%1, %2, %3, %4};"
                 :: "l"(addr), "f"(v.x), "f"(v.y), "f"(v.z), "f"(v.w)
                 : "memory");
}

// ---------------------------------------------------------------------------
// Shared tf32 MMA mainloop.
// 256 threads, 8 warps. Warp tile 32x64 (2 m16-tiles x 8 n8-tiles).
// PAIRED=0: warps tile BN as 2 cols of 64 (WN=2, BN=128).
// PAIRED=1: warps each own cols [wn*32,+32) and [BN/2+wn*32,+32) (WN=4, BN=256).
// K multiple of 32. A: [BM rows, lda>=K], B: [K rows, ldb], col base pre-applied.
// ---------------------------------------------------------------------------
#define ASW 36

template <int BM, int BN, int PAIRED>
__device__ __forceinline__ void mma_mainloop(
    const float* __restrict__ A, int lda,
    const float* __restrict__ B, int ldb,
    int K, float* As, float* Bs, float acc[2][8][4]) {
    const int BSW = BN + 8;
    int tid = threadIdx.x;
    int wid = tid >> 5;
    int lane = tid & 31;
    int g = lane >> 2;
    int t = lane & 3;
    const int WN = PAIRED ? 4 : 2;
    int wm = wid / WN;
    int wn = wid % WN;
    int mbase = wm * 32;

    for (int k0 = 0; k0 < K; k0 += 32) {
        // stage A tile: BM x 32 (tf32-rounded)
#pragma unroll
        for (int i = 0; i < BM * 32 / 1024; i++) {
            int f = tid + i * 256;
            int row = f >> 3;
            int c4 = (f & 7) * 4;
            float4 v = *(const float4*)(A + (size_t)row * lda + k0 + c4);
            v.x = f2tf32(v.x); v.y = f2tf32(v.y);
            v.z = f2tf32(v.z); v.w = f2tf32(v.w);
            *(float4*)(As + row * ASW + c4) = v;
        }
        // stage B tile: 32 x BN (tf32-rounded)
#pragma unroll
        for (int i = 0; i < BN * 32 / 1024; i++) {
            int f = tid + i * 256;
            int row = f / (BN / 4);
            int c4 = (f % (BN / 4)) * 4;
            float4 v = *(const float4*)(B + (size_t)(k0 + row) * ldb + c4);
            v.x = f2tf32(v.x); v.y = f2tf32(v.y);
            v.z = f2tf32(v.z); v.w = f2tf32(v.w);
            *(float4*)(Bs + row * BSW + c4) = v;
        }
        __syncthreads();
#pragma unroll
        for (int ks = 0; ks < 4; ks++) {
            int kk = ks * 8;
            uint32_t af[2][4];
#pragma unroll
            for (int mt = 0; mt < 2; mt++) {
                int r0 = mbase + mt * 16;
                af[mt][0] = __float_as_uint(As[(r0 + g) * ASW + kk + t]);
                af[mt][1] = __float_as_uint(As[(r0 + g + 8) * ASW + kk + t]);
                af[mt][2] = __float_as_uint(As[(r0 + g) * ASW + kk + t + 4]);
                af[mt][3] = __float_as_uint(As[(r0 + g + 8) * ASW + kk + t + 4]);
            }
#pragma unroll
            for (int nt = 0; nt < 8; nt++) {
                int cb = PAIRED ? (((nt & 4) ? BN / 2 : 0) + wn * 32 + (nt & 3) * 8)
                                : (wn * 64 + nt * 8);
                uint32_t b0 = __float_as_uint(Bs[(kk + t) * BSW + cb + g]);
                uint32_t b1 = __float_as_uint(Bs[(kk + t + 4) * BSW + cb + g]);
#pragma unroll
                for (int mt = 0; mt < 2; mt++) mma8(acc[mt][nt], af[mt], b0, b1);
            }
        }
        __syncthreads();
    }
}

// ---------------------------------------------------------------------------
// Node GEMM: C = act(A @ B + bias), 128x128 tiles.
// ---------------------------------------------------------------------------
template <int ACT>
__global__ void gemm_tc(const float* __restrict__ A, const float* __restrict__ B,
                        const float* __restrict__ bias, float* __restrict__ C,
                        int M, int N, int K) {
    __shared__ float As[128 * ASW];
    __shared__ float Bs[32 * 136];
    float acc[2][8][4];
#pragma unroll
    for (int i = 0; i < 2; i++)
#pragma unroll
        for (int j = 0; j < 8; j++)
#pragma unroll
            for (int k = 0; k < 4; k++) acc[i][j][k] = 0.f;

    int bm = blockIdx.y * 128;
    int bn = blockIdx.x * 128;
    mma_mainloop<128, 128, 0>(A + (size_t)bm * K, K, B + bn, N, K, As, Bs, acc);

    int tid = threadIdx.x;
    int wid = tid >> 5;
    int lane = tid & 31;
    int g = lane >> 2, t = lane & 3;
    int wm = wid >> 1, wn = wid & 1;

#pragma unroll
    for (int mt = 0; mt < 2; mt++) {
#pragma unroll
        for (int h = 0; h < 2; h++) {
            int r = bm + wm * 32 + mt * 16 + g + h * 8;
#pragma unroll
            for (int nt = 0; nt < 8; nt++) {
                int c = bn + wn * 64 + nt * 8 + 2 * t;
                float2 bb = *(const float2*)(bias + c);
                float vx = acc[mt][nt][2 * h + 0] + bb.x;
                float vy = acc[mt][nt][2 * h + 1] + bb.y;
                if (ACT) { vx = ssilu(vx); vy = ssilu(vy); }
                float2 o = {vx, vy};
                *(float2*)(C + (size_t)r * N + c) = o;
            }
        }
    }
}

// ---------------------------------------------------------------------------
// Edge kernel A: dx += xh1[src] * (ee @ Wr[:,0:128] + br[:128]); 128 edges/blk.
// ---------------------------------------------------------------------------
__global__ void edge_gemm_dx(const float* __restrict__ ee,
                             const float* __restrict__ Wr,
                             const float* __restrict__ br,
                             const int* __restrict__ ei) {
    __shared__ float As[128 * ASW];
    __shared__ float Bs[32 * 136];
    __shared__ int s_src[128];
    __shared__ int s_dst[128];
    int tid = threadIdx.x;
    int bm = blockIdx.x * 128;
    if (tid < 128) {
        s_src[tid] = ei[bm + tid];
        s_dst[tid] = ei[NE + bm + tid];
    }

    float acc[2][8][4];
#pragma unroll
    for (int i = 0; i < 2; i++)
#pragma unroll
        for (int j = 0; j < 8; j++)
#pragma unroll
            for (int k = 0; k < 4; k++) acc[i][j][k] = 0.f;

    mma_mainloop<128, 128, 0>(ee + (size_t)bm * 64, 64, Wr, 384, 64, As, Bs, acc);

    int wid = tid >> 5;
    int lane = tid & 31;
    int g = lane >> 2, t = lane & 3;
    int wm = wid >> 1, wn = wid & 1;

    float2 brv[8];
#pragma unroll
    for (int nt = 0; nt < 8; nt++)
        brv[nt] = *(const float2*)(br + wn * 64 + nt * 8 + 2 * t);

#pragma unroll
    for (int mt = 0; mt < 2; mt++) {
#pragma unroll
        for (int h = 0; h < 2; h++) {
            int rl = wm * 32 + mt * 16 + g + h * 8;
            int src = s_src[rl];
            int dst = s_dst[rl];
            const float* xhp = g_xh + (size_t)src * 384;
#pragma unroll
            for (int nt = 0; nt < 8; nt++) {
                int c = wn * 64 + nt * 8 + 2 * t;
                float2 x1 = *(const float2*)(xhp + c);
                float mx = (acc[mt][nt][2 * h + 0] + brv[nt].x) * x1.x;
                float my = (acc[mt][nt][2 * h + 1] + brv[nt].y) * x1.y;
                red2(g_dx + (size_t)dst * HD + c, mx, my);
            }
        }
    }
}

// ---------------------------------------------------------------------------
// Edge kernel B: dvec scatter. 64 edges x 256 cols (rbf2 | rbf3 paired).
// ---------------------------------------------------------------------------
__global__ void edge_gemm_dvec(const float* __restrict__ ee,
                               const float* __restrict__ Wr,
                               const float* __restrict__ br,
                               const int* __restrict__ ei,
                               const float* __restrict__ vec,
                               const float* __restrict__ evec) {
    __shared__ float As[64 * ASW];
    __shared__ float Bs[32 * 264];
    __shared__ int s_src[64];
    __shared__ int s_dst[64];
    __shared__ float s_ev[3][64];
    int tid = threadIdx.x;
    int bm = blockIdx.x * 64;
    if (tid < 64) {
        s_src[tid] = ei[bm + tid];
        s_dst[tid] = ei[NE + bm + tid];
    }
    if (tid < 192) {
        int e = tid & 63;
        int c = tid >> 6;
        s_ev[c][e] = evec[(size_t)(bm + e) * 3 + c];
    }

    float acc[2][8][4];
#pragma unroll
    for (int i = 0; i < 2; i++)
#pragma unroll
        for (int j = 0; j < 8; j++)
#pragma unroll
            for (int k = 0; k < 4; k++) acc[i][j][k] = 0.f;

    mma_mainloop<64, 256, 1>(ee + (size_t)bm * 64, 64, Wr + 128, 384, 64,
                             As, Bs, acc);

    int wid = tid >> 5;
    int lane = tid & 31;
    int g = lane >> 2, t = lane & 3;
    int wm = wid >> 2, wn = wid & 3;

    float2 b2v[4], b3v[4];
#pragma unroll
    for (int jt = 0; jt < 4; jt++) {
        int c = wn * 32 + jt * 8 + 2 * t;
        b2v[jt] = *(const float2*)(br + 128 + c);
        b3v[jt] = *(const float2*)(br + 256 + c);
    }

#pragma unroll
    for (int mt = 0; mt < 2; mt++) {
#pragma unroll
        for (int h = 0; h < 2; h++) {
            int rl = wm * 32 + mt * 16 + g + h * 8;
            int src = s_src[rl];
            int dst = s_dst[rl];
            float ev0 = s_ev[0][rl], ev1 = s_ev[1][rl], ev2 = s_ev[2][rl];
            const float* xhp = g_xh + (size_t)src * 384;
            const float* vp = vec + (size_t)src * 384;
            float* dvp = g_dvec + (size_t)dst * 384;
#pragma unroll
            for (int jt = 0; jt < 4; jt++) {
                int c = wn * 32 + jt * 8 + 2 * t;   // h-index in [0,128)
                float2 x2 = *(const float2*)(xhp + 128 + c);
                float2 x3 = *(const float2*)(xhp + 256 + c);
                float m2x = (acc[mt][jt][2 * h + 0] + b2v[jt].x) * x2.x * C_INV_SQRT_3;
                float m2y = (acc[mt][jt][2 * h + 1] + b2v[jt].y) * x2.y * C_INV_SQRT_3;
                float m3x = (acc[mt][jt + 4][2 * h + 0] + b3v[jt].x) * x3.x;
                float m3y = (acc[mt][jt + 4][2 * h + 1] + b3v[jt].y) * x3.y;
                {
                    float2 vv = *(const float2*)(vp + 0 * 128 + c);
                    red2(dvp + 0 * 128 + c,
                         (vv.x * m2x + m3x * ev0) * C_INV_SQRT_H,
                         (vv.y * m2y + m3y * ev0) * C_INV_SQRT_H);
                }
                {
                    float2 vv = *(const float2*)(vp + 1 * 128 + c);
                    red2(dvp + 1 * 128 + c,
                         (vv.x * m2x + m3x * ev1) * C_INV_SQRT_H,
                         (vv.y * m2y + m3y * ev1) * C_INV_SQRT_H);
                }
                {
                    float2 vv = *(const float2*)(vp + 2 * 128 + c);
                    red2(dvp + 2 * 128 + c,
                         (vv.x * m2x + m3x * ev2) * C_INV_SQRT_H,
                         (vv.y * m2y + m3y * ev2) * C_INV_SQRT_H);
                }
            }
        }
    }
}

// ---------------------------------------------------------------------------
__global__ void zero_acc_kernel() {
    int total4 = (NN * HD + NN * 3 * HD) / 4;
    float4 z = make_float4(0.f, 0.f, 0.f, 0.f);
    for (int i = blockIdx.x * blockDim.x + threadIdx.x; i < total4;
         i += gridDim.x * blockDim.x) {
        if (i < NN * HD / 4)
            ((float4*)g_dx)[i] = z;
        else
            ((float4*)g_dvec)[i - NN * HD / 4] = z;
    }
}

// ---------------------------------------------------------------------------
__global__ void ln_kernel(const float* __restrict__ x,
                          const float* __restrict__ g,
                          const float* __restrict__ b) {
    int row = blockIdx.x * (blockDim.x >> 5) + (threadIdx.x >> 5);
    int lane = threadIdx.x & 31;
    if (row >= NN) return;
    float4 v = *(const float4*)(x + (size_t)row * HD + lane * 4);
    float s = v.x + v.y + v.z + v.w;
    float s2 = v.x * v.x + v.y * v.y + v.z * v.z + v.w * v.w;
#pragma unroll
    for (int o = 16; o > 0; o >>= 1) {
        s += __shfl_xor_sync(0xffffffffu, s, o);
        s2 += __shfl_xor_sync(0xffffffffu, s2, o);
    }
    float mu = s * (1.0f / HD);
    float var = s2 * (1.0f / HD) - mu * mu;
    float inv = rsqrtf(var + 1e-5f);
    float4 gg = *(const float4*)(g + lane * 4);
    float4 bb = *(const float4*)(b + lane * 4);
    float4 o4;
    o4.x = (v.x - mu) * inv * gg.x + bb.x;
    o4.y = (v.y - mu) * inv * gg.y + bb.y;
    o4.z = (v.z - mu) * inv * gg.z + bb.z;
    o4.w = (v.w - mu) * inv * gg.w + bb.w;
    *(float4*)(g_xln + (size_t)row * HD + lane * 4) = o4;
}

// ---------------------------------------------------------------------------
__global__ void node_mid_kernel(const float* __restrict__ x,
                                const float* __restrict__ vec) {
    int i = blockIdx.x * blockDim.x + threadIdx.x;
    if (i < NN * 3 * HD) g_vecnew[i] = vec[i] + g_dvec[i];
    if (i < NN * HD) g_xnew[i] = (x[i] + g_dx[i]) * C_INV_SQRT_2;
}

// ---------------------------------------------------------------------------
__global__ void dotnorm_kernel() {
    int i = blockIdx.x * blockDim.x + threadIdx.x;
    if (i >= NN * HD) return;
    int n = i >> 7;
    int h = i & 127;
    const float* vp = g_vproj + (size_t)n * 768;
    float d = 0.f, s = 0.f;
#pragma unroll
    for (int c = 0; c < 3; c++) {
        float v1 = vp[c * 256 + h];
        float v2 = vp[c * 256 + 128 + h];
        d += v1 * v2;
        s += v2 * v2;
    }
    g_vecdot[i] = d * C_INV_SQRT_H;
    g_cat[(size_t)n * 256 + h] = g_xnew[i];
    g_cat[(size_t)n * 256 + 128 + h] = sqrtf(s + 1e-8f);
}

// ---------------------------------------------------------------------------
__global__ void finalize_kernel(float* __restrict__ out) {
    int i = blockIdx.x * blockDim.x + threadIdx.x;
    if (i >= NN * HD) return;
    int n = i >> 7;
    int h = i & 127;
    const float* hb = g_hbuf + (size_t)n * 384;
    float xv1 = hb[h];
    float xv2 = hb[128 + h];
    float xv3 = hb[256 + h];
    float* out_vec = out;
    float* out_x = out + (size_t)NN * 3 * HD;
    out_x[i] = g_xnew[i] + (xv1 + xv2 * g_vecdot[i]) * C_INV_SQRT_2;
#pragma unroll
    for (int c = 0; c < 3; c++) {
        size_t idx = (size_t)n * 384 + c * HD + h;
        out_vec[idx] = g_vecnew[idx] + xv3 * g_vproj[(size_t)n * 768 + c * 256 + h];
    }
}

// ---------------------------------------------------------------------------
extern "C" void kernel_launch(void* const* d_in, const int* in_sizes, int n_in,
                              void* d_out, int out_size) {
    const float* x    = (const float*)d_in[0];
    const float* vec  = (const float*)d_in[1];
    const int*   ei   = (const int*)d_in[2];
    const float* ee   = (const float*)d_in[3];
    const float* evec = (const float*)d_in[4];
    const float* ln_g = (const float*)d_in[5];
    const float* ln_b = (const float*)d_in[6];
    const float* W1   = (const float*)d_in[7];
    const float* b1   = (const float*)d_in[8];
    const float* W2   = (const float*)d_in[9];
    const float* b2   = (const float*)d_in[10];
    const float* Wr   = (const float*)d_in[11];
    const float* br   = (const float*)d_in[12];
    const float* Wv   = (const float*)d_in[13];
    const float* Wu1  = (const float*)d_in[14];
    const float* bu1  = (const float*)d_in[15];
    const float* Wu2  = (const float*)d_in[16];
    const float* bu2  = (const float*)d_in[17];

    float* out = (float*)d_out;

    float* zb = nullptr;     cudaGetSymbolAddress((void**)&zb, g_zerobias);
    float* xln = nullptr;    cudaGetSymbolAddress((void**)&xln, g_xln);
    float* t1 = nullptr;     cudaGetSymbolAddress((void**)&t1, g_t1);
    float* xh = nullptr;     cudaGetSymbolAddress((void**)&xh, g_xh);
    float* vecnew = nullptr; cudaGetSymbolAddress((void**)&vecnew, g_vecnew);
    float* vproj = nullptr;  cudaGetSymbolAddress((void**)&vproj, g_vproj);
    float* cat = nullptr;    cudaGetSymbolAddress((void**)&cat, g_cat);
    float* u = nullptr;      cudaGetSymbolAddress((void**)&u, g_u);
    float* hbuf = nullptr;   cudaGetSymbolAddress((void**)&hbuf, g_hbuf);

    // 1. zero dx/dvec accumulators
    zero_acc_kernel<<<4096, 256>>>();

    // 2. LayerNorm
    ln_kernel<<<NN / 8, 256>>>(x, ln_g, ln_b);

    // 3. t1 = scaled_silu(xln @ W1 + b1)
    gemm_tc<1><<<dim3(1, NN / 128), 256>>>(xln, W1, b1, t1, NN, 128, 128);

    // 4. xh = t1 @ W2 + b2
    gemm_tc<0><<<dim3(3, NN / 128), 256>>>(t1, W2, b2, xh, NN, 384, 128);

    // 5+6. fused rbfh GEMM + edge message + scatter
    edge_gemm_dx<<<NE / 128, 256>>>(ee, Wr, br, ei);
    edge_gemm_dvec<<<NE / 64, 256>>>(ee, Wr, br, ei, vec, evec);

    // 7. x_new, vec_new
    node_mid_kernel<<<(NN * 3 * HD + 255) / 256, 256>>>(x, vec);

    // 8. vproj = vec_new(3N,128) @ Wv(128,256)
    gemm_tc<0><<<dim3(2, (3 * NN) / 128), 256>>>(vecnew, Wv, zb, vproj,
                                                 3 * NN, 256, 128);

    // 9. vec_dot / vec2_norm / cat
    dotnorm_kernel<<<(NN * HD) / 256, 256>>>();

    // 10. u = scaled_silu(cat @ Wu1 + bu1)
    gemm_tc<1><<<dim3(1, NN / 128), 256>>>(cat, Wu1, bu1, u, NN, 128, 256);

    // 11. h = u @ Wu2 + bu2
    gemm_tc<0><<<dim3(3, NN / 128), 256>>>(u, Wu2, bu2, hbuf, NN, 384, 128);

    // 12. finalize
    finalize_kernel<<<(NN * HD) / 256, 256>>>(out);
}

// round 4
// speedup vs baseline: 1.9492x; 1.2431x over previous
#include <cuda_runtime.h>
#include <math.h>
#include <stdint.h>

#define NN 32768
#define NE 524288
#define HD 128
#define ASW 36

__device__ __forceinline__ float ssilu(float v) {
    return v / ((1.0f + __expf(-v)) * 0.6f);
}
__device__ __forceinline__ float f2tf32(float x) {
    float r;
    asm("cvt.rna.tf32.f32 %0, %1;" : "=f"(r) : "f"(x));
    return r;
}
__device__ __forceinline__ float4 rnd4(float4 v) {
    v.x = f2tf32(v.x); v.y = f2tf32(v.y);
    v.z = f2tf32(v.z); v.w = f2tf32(v.w);
    return v;
}

// scratch ------------------------------------------------------------------
static __device__ float g_xln[NN * HD];
static __device__ float g_t1[NN * HD];
static __device__ float g_xh[NN * 3 * HD];
static __device__ float g_dx[NN * HD];
static __device__ float g_dvec[NN * 3 * HD];
static __device__ float g_xnew[NN * HD];
static __device__ float g_vecnew[NN * 3 * HD];
static __device__ float g_vecnewtf[NN * 3 * HD];
static __device__ float g_vproj[NN * 3 * 2 * HD];
static __device__ float g_vecdot[NN * HD];
static __device__ float g_cat[NN * 2 * HD];
static __device__ float g_u[NN * HD];
static __device__ float g_hbuf[NN * 3 * HD];
static __device__ float g_zerobias[512];
static __device__ float g_eetf[(size_t)NE * 64];
static __device__ float g_W1t[128 * 128];
static __device__ float g_W2t[128 * 384];
static __device__ float g_Wrt[64 * 384];
static __device__ float g_Wvt[128 * 256];
static __device__ float g_Wu1t[256 * 128];
static __device__ float g_Wu2t[128 * 384];

__constant__ float C_INV_SQRT_3 = 0.57735026918962576451f;
__constant__ float C_INV_SQRT_H = 0.08838834764831844055f;
__constant__ float C_INV_SQRT_2 = 0.70710678118654752440f;

// ---------------------------------------------------------------------------
__device__ __forceinline__ void cp16(float* s, const float* g) {
    uint32_t sa = (uint32_t)__cvta_generic_to_shared(s);
    asm volatile("cp.async.cg.shared.global [%0], [%1], 16;"
                 :: "r"(sa), "l"(g) : "memory");
}
__device__ __forceinline__ void mma8(float c[4], const uint32_t a[4],
                                     uint32_t b0, uint32_t b1) {
    asm volatile(
        "mma.sync.aligned.m16n8k8.row.col.f32.tf32.tf32.f32 "
        "{%0,%1,%2,%3}, {%4,%5,%6,%7}, {%8,%9}, {%0,%1,%2,%3};"
        : "+f"(c[0]), "+f"(c[1]), "+f"(c[2]), "+f"(c[3])
        : "r"(a[0]), "r"(a[1]), "r"(a[2]), "r"(a[3]), "r"(b0), "r"(b1));
}
__device__ __forceinline__ void red4(float* addr, float4 v) {
    asm volatile("red.global.add.v4.f32 [%0], {%1, %2, %3, %4};"
                 :: "l"(addr), "f"(v.x), "f"(v.y), "f"(v.z), "f"(v.w)
                 : "memory");
}

// ---------------------------------------------------------------------------
// Double-buffered tf32 MMA mainloop. Inputs must already be tf32-rounded.
// 256 threads, 8 warps, warp tile 32x64. BN in {128,256}. K % 32 == 0.
// sm layout: As[2][BM*ASW] then Bs[2][32*(BN+8)].
// ---------------------------------------------------------------------------
template <int BM, int BN>
__device__ __forceinline__ void mma_loop(
    const float* __restrict__ A, int lda,
    const float* __restrict__ B, int ldb, int K,
    float* sm, float acc[2][8][4]) {
    const int BSW = BN + 8;
    const int ABUF = BM * ASW;
    const int BBUF = 32 * BSW;
    float* As = sm;
    float* Bs = sm + 2 * ABUF;
    int tid = threadIdx.x;
    int wid = tid >> 5, lane = tid & 31;
    int g = lane >> 2, t = lane & 3;
    const int WN = BN / 64;
    int wm = wid / WN, wn = wid % WN;
    int mbase = wm * 32;

    // prologue: stage chunk 0
    {
        float* as = As;
        float* bs = Bs;
#pragma unroll
        for (int i = 0; i < BM / 32; i++) {
            int f = tid + i * 256;
            int row = f >> 3, c4 = (f & 7) * 4;
            cp16(as + row * ASW + c4, A + (size_t)row * lda + c4);
        }
#pragma unroll
        for (int i = 0; i < BN / 32; i++) {
            int f = tid + i * 256;
            int row = f / (BN / 4), c4 = (f % (BN / 4)) * 4;
            cp16(bs + row * BSW + c4, B + (size_t)row * ldb + c4);
        }
        asm volatile("cp.async.commit_group;" ::: "memory");
    }

    int nk = K >> 5;
    for (int kc = 0; kc < nk; kc++) {
        if (kc + 1 < nk) {
            int k0 = (kc + 1) * 32;
            float* as = As + ((kc + 1) & 1) * ABUF;
            float* bs = Bs + ((kc + 1) & 1) * BBUF;
#pragma unroll
            for (int i = 0; i < BM / 32; i++) {
                int f = tid + i * 256;
                int row = f >> 3, c4 = (f & 7) * 4;
                cp16(as + row * ASW + c4, A + (size_t)row * lda + k0 + c4);
            }
#pragma unroll
            for (int i = 0; i < BN / 32; i++) {
                int f = tid + i * 256;
                int row = f / (BN / 4), c4 = (f % (BN / 4)) * 4;
                cp16(bs + row * BSW + c4, B + (size_t)(k0 + row) * ldb + c4);
            }
            asm volatile("cp.async.commit_group;" ::: "memory");
            asm volatile("cp.async.wait_group 1;" ::: "memory");
        } else {
            asm volatile("cp.async.wait_group 0;" ::: "memory");
        }
        __syncthreads();
        const float* as = As + (kc & 1) * ABUF;
        const float* bs = Bs + (kc & 1) * BBUF;
#pragma unroll
        for (int ks = 0; ks < 4; ks++) {
            int kk = ks * 8;
            uint32_t af[2][4];
#pragma unroll
            for (int mt = 0; mt < 2; mt++) {
                int r0 = mbase + mt * 16;
                af[mt][0] = __float_as_uint(as[(r0 + g) * ASW + kk + t]);
                af[mt][1] = __float_as_uint(as[(r0 + g + 8) * ASW + kk + t]);
                af[mt][2] = __float_as_uint(as[(r0 + g) * ASW + kk + t + 4]);
                af[mt][3] = __float_as_uint(as[(r0 + g + 8) * ASW + kk + t + 4]);
            }
#pragma unroll
            for (int nt = 0; nt < 8; nt++) {
                int cb = wn * 64 + nt * 8;
                uint32_t b0 = __float_as_uint(bs[(kk + t) * BSW + cb + g]);
                uint32_t b1 = __float_as_uint(bs[(kk + t + 4) * BSW + cb + g]);
#pragma unroll
                for (int mt = 0; mt < 2; mt++) mma8(acc[mt][nt], af[mt], b0, b1);
            }
        }
        __syncthreads();
    }
}

#define ACC_INIT(acc)                                   \
    _Pragma("unroll") for (int i = 0; i < 2; i++)       \
    _Pragma("unroll") for (int j = 0; j < 8; j++)       \
    _Pragma("unroll") for (int k = 0; k < 4; k++) acc[i][j][k] = 0.f;

// ---------------------------------------------------------------------------
// Node GEMM: C = act(A @ B + bias), 128x128 tile. RND rounds output to tf32.
// ---------------------------------------------------------------------------
template <int ACT, int RND>
__global__ void __launch_bounds__(256, 2)
gemm_tc(const float* __restrict__ A, const float* __restrict__ B,
        const float* __restrict__ bias, float* __restrict__ C,
        int M, int N, int K) {
    extern __shared__ float sm[];
    float acc[2][8][4];
    ACC_INIT(acc)
    int bm = blockIdx.y * 128;
    int bn = blockIdx.x * 128;
    mma_loop<128, 128>(A + (size_t)bm * K, K, B + bn, N, K, sm, acc);

    int tid = threadIdx.x;
    int wid = tid >> 5, lane = tid & 31;
    int g = lane >> 2, t = lane & 3;
    int wm = wid >> 1, wn = wid & 1;
#pragma unroll
    for (int mt = 0; mt < 2; mt++) {
#pragma unroll
        for (int h = 0; h < 2; h++) {
            int r = bm + wm * 32 + mt * 16 + g + h * 8;
#pragma unroll
            for (int nt = 0; nt < 8; nt++) {
                int c = bn + wn * 64 + nt * 8 + 2 * t;
                float2 bb = *(const float2*)(bias + c);
                float vx = acc[mt][nt][2 * h + 0] + bb.x;
                float vy = acc[mt][nt][2 * h + 1] + bb.y;
                if (ACT) { vx = ssilu(vx); vy = ssilu(vy); }
                if (RND) { vx = f2tf32(vx); vy = f2tf32(vy); }
                float2 o = {vx, vy};
                *(float2*)(C + (size_t)r * N + c) = o;
            }
        }
    }
}

// ---------------------------------------------------------------------------
// Edge kernel A: dx += xh1[src] * (ee @ Wr[:,0:128] + br[:128]).
// 128 edges/block; SMEM-transpose epilogue -> float4 gather + red4 scatter.
// ---------------------------------------------------------------------------
__global__ void __launch_bounds__(256, 2)
edge_gemm_dx(const float* __restrict__ br, const int* __restrict__ ei) {
    extern __shared__ float sm[];
    __shared__ int s_src[128];
    __shared__ int s_dst[128];
    int tid = threadIdx.x;
    int bm = blockIdx.x * 128;
    if (tid < 128) {
        s_src[tid] = ei[bm + tid];
        s_dst[tid] = ei[NE + bm + tid];
    }
    float acc[2][8][4];
    ACC_INIT(acc)
    mma_loop<128, 128>(g_eetf + (size_t)bm * 64, 64, g_Wrt, 384, 64, sm, acc);

    int wid = tid >> 5, lane = tid & 31;
    int g = lane >> 2, t = lane & 3;
    int wm = wid >> 1, wn = wid & 1;
    float* sbuf = sm;   // 128 x 132, mainloop buffers are dead now
#pragma unroll
    for (int mt = 0; mt < 2; mt++) {
#pragma unroll
        for (int h = 0; h < 2; h++) {
            int row = wm * 32 + mt * 16 + g + h * 8;
#pragma unroll
            for (int nt = 0; nt < 8; nt++) {
                int col = wn * 64 + nt * 8 + 2 * t;
                float2 bb = *(const float2*)(br + col);
                sbuf[row * 132 + col]     = acc[mt][nt][2 * h + 0] + bb.x;
                sbuf[row * 132 + col + 1] = acc[mt][nt][2 * h + 1] + bb.y;
            }
        }
    }
    __syncthreads();
#pragma unroll
    for (int i = 0; i < 16; i++) {
        int f = tid + i * 256;
        int e = f >> 5;
        int c4 = (f & 31) * 4;
        int src = s_src[e], dst = s_dst[e];
        float4 m = *(float4*)(sbuf + e * 132 + c4);
        float4 x1 = *(const float4*)(g_xh + (size_t)src * 384 + c4);
        m.x *= x1.x; m.y *= x1.y; m.z *= x1.z; m.w *= x1.w;
        red4(g_dx + (size_t)dst * HD + c4, m);
    }
}

// ---------------------------------------------------------------------------
// Edge kernel B: dvec scatter. 64 edges x 256 cols (rbf2 | rbf3).
// ---------------------------------------------------------------------------
__global__ void __launch_bounds__(256, 2)
edge_gemm_dvec(const float* __restrict__ br, const int* __restrict__ ei,
               const float* __restrict__ vec, const float* __restrict__ evec) {
    extern __shared__ float sm[];
    __shared__ int s_src[64];
    __shared__ int s_dst[64];
    __shared__ float s_ev[3][64];
    int tid = threadIdx.x;
    int bm = blockIdx.x * 64;
    if (tid < 64) {
        s_src[tid] = ei[bm + tid];
        s_dst[tid] = ei[NE + bm + tid];
    }
    if (tid < 192) {
        int e = tid & 63;
        int c = tid >> 6;
        s_ev[c][e] = evec[(size_t)(bm + e) * 3 + c];
    }
    float acc[2][8][4];
    ACC_INIT(acc)
    mma_loop<64, 256>(g_eetf + (size_t)bm * 64, 64, g_Wrt + 128, 384, 64,
                      sm, acc);

    int wid = tid >> 5, lane = tid & 31;
    int g = lane >> 2, t = lane & 3;
    int wm = wid >> 2, wn = wid & 3;
    float* sbuf = sm;   // 64 x 260
#pragma unroll
    for (int mt = 0; mt < 2; mt++) {
#pragma unroll
        for (int h = 0; h < 2; h++) {
            int row = wm * 32 + mt * 16 + g + h * 8;
#pragma unroll
            for (int nt = 0; nt < 8; nt++) {
                int col = wn * 64 + nt * 8 + 2 * t;
                float2 bb = *(const float2*)(br + 128 + col);
                sbuf[row * 260 + col]     = acc[mt][nt][2 * h + 0] + bb.x;
                sbuf[row * 260 + col + 1] = acc[mt][nt][2 * h + 1] + bb.y;
            }
        }
    }
    __syncthreads();
#pragma unroll
    for (int i = 0; i < 8; i++) {
        int f = tid + i * 256;
        int e = f >> 5;
        int c4 = (f & 31) * 4;
        int src = s_src[e], dst = s_dst[e];
        float ev0 = s_ev[0][e], ev1 = s_ev[1][e], ev2 = s_ev[2][e];
        float4 r2 = *(float4*)(sbuf + e * 260 + c4);
        float4 r3 = *(float4*)(sbuf + e * 260 + 128 + c4);
        const float* xhp = g_xh + (size_t)src * 384;
        float4 x2 = *(const float4*)(xhp + 128 + c4);
        float4 x3 = *(const float4*)(xhp + 256 + c4);
        float4 m2, m3;
        m2.x = r2.x * x2.x * C_INV_SQRT_3; m2.y = r2.y * x2.y * C_INV_SQRT_3;
        m2.z = r2.z * x2.z * C_INV_SQRT_3; m2.w = r2.w * x2.w * C_INV_SQRT_3;
        m3.x = r3.x * x3.x; m3.y = r3.y * x3.y;
        m3.z = r3.z * x3.z; m3.w = r3.w * x3.w;
        const float* vp = vec + (size_t)src * 384;
        float* dvp = g_dvec + (size_t)dst * 384;
#pragma unroll
        for (int c = 0; c < 3; c++) {
            float ev = (c == 0) ? ev0 : ((c == 1) ? ev1 : ev2);
            float4 vv = *(const float4*)(vp + c * 128 + c4);
            float4 msg;
            msg.x = (vv.x * m2.x + m3.x * ev) * C_INV_SQRT_H;
            msg.y = (vv.y * m2.y + m3.y * ev) * C_INV_SQRT_H;
            msg.z = (vv.z * m2.z + m3.z * ev) * C_INV_SQRT_H;
            msg.w = (vv.w * m2.w + m3.w * ev) * C_INV_SQRT_H;
            red4(dvp + c * 128 + c4, msg);
        }
    }
}

// ---------------------------------------------------------------------------
__global__ void zero_acc_kernel() {
    int total4 = (NN * HD + NN * 3 * HD) / 4;
    float4 z = make_float4(0.f, 0.f, 0.f, 0.f);
    for (int i = blockIdx.x * blockDim.x + threadIdx.x; i < total4;
         i += gridDim.x * blockDim.x) {
        if (i < NN * HD / 4)
            ((float4*)g_dx)[i] = z;
        else
            ((float4*)g_dvec)[i - NN * HD / 4] = z;
    }
}

// round ee -> g_eetf (tf32) ---------------------------------------------------
__global__ void round_ee_kernel(const float* __restrict__ ee) {
    int total4 = NE * 64 / 4;
    for (int i = blockIdx.x * blockDim.x + threadIdx.x; i < total4;
         i += gridDim.x * blockDim.x) {
        ((float4*)g_eetf)[i] = rnd4(((const float4*)ee)[i]);
    }
}

// round all weights -> tf32 copies -------------------------------------------
__global__ void round_w_kernel(const float* __restrict__ W1,
                               const float* __restrict__ W2,
                               const float* __restrict__ Wr,
                               const float* __restrict__ Wv,
                               const float* __restrict__ Wu1,
                               const float* __restrict__ Wu2) {
    const int s1 = 128 * 128 / 4, s2 = 128 * 384 / 4, s3 = 64 * 384 / 4;
    const int s4 = 128 * 256 / 4, s5 = 256 * 128 / 4, s6 = 128 * 384 / 4;
    int i = blockIdx.x * blockDim.x + threadIdx.x;
    int stride = gridDim.x * blockDim.x;
    for (; i < s1 + s2 + s3 + s4 + s5 + s6; i += stride) {
        int j = i;
        if (j < s1) { ((float4*)g_W1t)[j] = rnd4(((const float4*)W1)[j]); continue; }
        j -= s1;
        if (j < s2) { ((float4*)g_W2t)[j] = rnd4(((const float4*)W2)[j]); continue; }
        j -= s2;
        if (j < s3) { ((float4*)g_Wrt)[j] = rnd4(((const float4*)Wr)[j]); continue; }
        j -= s3;
        if (j < s4) { ((float4*)g_Wvt)[j] = rnd4(((const float4*)Wv)[j]); continue; }
        j -= s4;
        if (j < s5) { ((float4*)g_Wu1t)[j] = rnd4(((const float4*)Wu1)[j]); continue; }
        j -= s5;
        ((float4*)g_Wu2t)[j] = rnd4(((const float4*)Wu2)[j]);
    }
}

// ---------------------------------------------------------------------------
__global__ void ln_kernel(const float* __restrict__ x,
                          const float* __restrict__ g,
                          const float* __restrict__ b) {
    int row = blockIdx.x * (blockDim.x >> 5) + (threadIdx.x >> 5);
    int lane = threadIdx.x & 31;
    if (row >= NN) return;
    float4 v = *(const float4*)(x + (size_t)row * HD + lane * 4);
    float s = v.x + v.y + v.z + v.w;
    float s2 = v.x * v.x + v.y * v.y + v.z * v.z + v.w * v.w;
#pragma unroll
    for (int o = 16; o > 0; o >>= 1) {
        s += __shfl_xor_sync(0xffffffffu, s, o);
        s2 += __shfl_xor_sync(0xffffffffu, s2, o);
    }
    float mu = s * (1.0f / HD);
    float var = s2 * (1.0f / HD) - mu * mu;
    float inv = rsqrtf(var + 1e-5f);
    float4 gg = *(const float4*)(g + lane * 4);
    float4 bb = *(const float4*)(b + lane * 4);
    float4 o4;
    o4.x = f2tf32((v.x - mu) * inv * gg.x + bb.x);
    o4.y = f2tf32((v.y - mu) * inv * gg.y + bb.y);
    o4.z = f2tf32((v.z - mu) * inv * gg.z + bb.z);
    o4.w = f2tf32((v.w - mu) * inv * gg.w + bb.w);
    *(float4*)(g_xln + (size_t)row * HD + lane * 4) = o4;
}

// ---------------------------------------------------------------------------
__global__ void node_mid_kernel(const float* __restrict__ x,
                                const float* __restrict__ vec) {
    int i = blockIdx.x * blockDim.x + threadIdx.x;
    if (i < NN * 3 * HD) {
        float vn = vec[i] + g_dvec[i];
        g_vecnew[i] = vn;
        g_vecnewtf[i] = f2tf32(vn);
    }
    if (i < NN * HD) g_xnew[i] = (x[i] + g_dx[i]) * C_INV_SQRT_2;
}

// ---------------------------------------------------------------------------
__global__ void dotnorm_kernel() {
    int i = blockIdx.x * blockDim.x + threadIdx.x;
    if (i >= NN * HD) return;
    int n = i >> 7;
    int h = i & 127;
    const float* vp = g_vproj + (size_t)n * 768;
    float d = 0.f, s = 0.f;
#pragma unroll
    for (int c = 0; c < 3; c++) {
        float v1 = vp[c * 256 + h];
        float v2 = vp[c * 256 + 128 + h];
        d += v1 * v2;
        s += v2 * v2;
    }
    g_vecdot[i] = d * C_INV_SQRT_H;
    g_cat[(size_t)n * 256 + h] = f2tf32(g_xnew[i]);
    g_cat[(size_t)n * 256 + 128 + h] = f2tf32(sqrtf(s + 1e-8f));
}

// ---------------------------------------------------------------------------
__global__ void finalize_kernel(float* __restrict__ out) {
    int i = blockIdx.x * blockDim.x + threadIdx.x;
    if (i >= NN * HD) return;
    int n = i >> 7;
    int h = i & 127;
    const float* hb = g_hbuf + (size_t)n * 384;
    float xv1 = hb[h];
    float xv2 = hb[128 + h];
    float xv3 = hb[256 + h];
    float* out_vec = out;
    float* out_x = out + (size_t)NN * 3 * HD;
    out_x[i] = g_xnew[i] + (xv1 + xv2 * g_vecdot[i]) * C_INV_SQRT_2;
#pragma unroll
    for (int c = 0; c < 3; c++) {
        size_t idx = (size_t)n * 384 + c * HD + h;
        out_vec[idx] = g_vecnew[idx] + xv3 * g_vproj[(size_t)n * 768 + c * 256 + h];
    }
}

// ---------------------------------------------------------------------------
extern "C" void kernel_launch(void* const* d_in, const int* in_sizes, int n_in,
                              void* d_out, int out_size) {
    const float* x    = (const float*)d_in[0];
    const float* vec  = (const float*)d_in[1];
    const int*   ei   = (const int*)d_in[2];
    const float* ee   = (const float*)d_in[3];
    const float* evec = (const float*)d_in[4];
    const float* ln_g = (const float*)d_in[5];
    const float* ln_b = (const float*)d_in[6];
    const float* W1   = (const float*)d_in[7];
    const float* b1   = (const float*)d_in[8];
    const float* W2   = (const float*)d_in[9];
    const float* b2   = (const float*)d_in[10];
    const float* Wr   = (const float*)d_in[11];
    const float* br   = (const float*)d_in[12];
    const float* Wv   = (const float*)d_in[13];
    const float* Wu1  = (const float*)d_in[14];
    const float* bu1  = (const float*)d_in[15];
    const float* Wu2  = (const float*)d_in[16];
    const float* bu2  = (const float*)d_in[17];

    float* out = (float*)d_out;

    float* zb = nullptr;      cudaGetSymbolAddress((void**)&zb, g_zerobias);
    float* xln = nullptr;     cudaGetSymbolAddress((void**)&xln, g_xln);
    float* t1 = nullptr;      cudaGetSymbolAddress((void**)&t1, g_t1);
    float* xh = nullptr;      cudaGetSymbolAddress((void**)&xh, g_xh);
    float* vecnewtf = nullptr; cudaGetSymbolAddress((void**)&vecnewtf, g_vecnewtf);
    float* vproj = nullptr;   cudaGetSymbolAddress((void**)&vproj, g_vproj);
    float* cat = nullptr;     cudaGetSymbolAddress((void**)&cat, g_cat);
    float* u = nullptr;       cudaGetSymbolAddress((void**)&u, g_u);
    float* hbuf = nullptr;    cudaGetSymbolAddress((void**)&hbuf, g_hbuf);
    float* w1t = nullptr;     cudaGetSymbolAddress((void**)&w1t, g_W1t);
    float* w2t = nullptr;     cudaGetSymbolAddress((void**)&w2t, g_W2t);
    float* wvt = nullptr;     cudaGetSymbolAddress((void**)&wvt, g_Wvt);
    float* wu1t = nullptr;    cudaGetSymbolAddress((void**)&wu1t, g_Wu1t);
    float* wu2t = nullptr;    cudaGetSymbolAddress((void**)&wu2t, g_Wu2t);

    const int SMEM_NODE = (2 * 128 * ASW + 2 * 32 * 136) * 4;   // 71680 B
    const int SMEM_DVEC = (2 * 64 * ASW + 2 * 32 * 264) * 4;    // 86016 B

    cudaFuncSetAttribute((const void*)gemm_tc<0, 0>,
                         cudaFuncAttributeMaxDynamicSharedMemorySize, SMEM_NODE);
    cudaFuncSetAttribute((const void*)gemm_tc<1, 1>,
                         cudaFuncAttributeMaxDynamicSharedMemorySize, SMEM_NODE);
    cudaFuncSetAttribute((const void*)edge_gemm_dx,
                         cudaFuncAttributeMaxDynamicSharedMemorySize, SMEM_NODE);
    cudaFuncSetAttribute((const void*)edge_gemm_dvec,
                         cudaFuncAttributeMaxDynamicSharedMemorySize, SMEM_DVEC);

    // prep: zero accumulators, round ee + weights to tf32
    zero_acc_kernel<<<2048, 256>>>();
    round_ee_kernel<<<4096, 256>>>(ee);
    round_w_kernel<<<256, 256>>>(W1, W2, Wr, Wv, Wu1, Wu2);

    // LayerNorm (tf32-rounded output)
    ln_kernel<<<NN / 8, 256>>>(x, ln_g, ln_b);

    // t1 = rna(scaled_silu(xln @ W1 + b1))
    gemm_tc<1, 1><<<dim3(1, NN / 128), 256, SMEM_NODE>>>(xln, w1t, b1, t1,
                                                         NN, 128, 128);
    // xh = t1 @ W2 + b2   (fp32 out; consumed by epilogues, not MMA)
    gemm_tc<0, 0><<<dim3(3, NN / 128), 256, SMEM_NODE>>>(t1, w2t, b2, xh,
                                                         NN, 384, 128);

    // fused rbfh GEMM + message + scatter
    edge_gemm_dx<<<NE / 128, 256, SMEM_NODE>>>(br, ei);
    edge_gemm_dvec<<<NE / 64, 256, SMEM_DVEC>>>(br, ei, vec, evec);

    // x_new, vec_new (+ tf32 copy of vec_new for the Wv GEMM)
    node_mid_kernel<<<(NN * 3 * HD + 255) / 256, 256>>>(x, vec);

    // vproj = vec_new @ Wv
    gemm_tc<0, 0><<<dim3(2, (3 * NN) / 128), 256, SMEM_NODE>>>(
        vecnewtf, wvt, zb, vproj, 3 * NN, 256, 128);

    // vec_dot / vec2_norm / cat (tf32)
    dotnorm_kernel<<<(NN * HD) / 256, 256>>>();

    // u = rna(scaled_silu(cat @ Wu1 + bu1))
    gemm_tc<1, 1><<<dim3(1, NN / 128), 256, SMEM_NODE>>>(cat, wu1t, bu1, u,
                                                         NN, 128, 256);
    // hbuf = u @ Wu2 + bu2
    gemm_tc<0, 0><<<dim3(3, NN / 128), 256, SMEM_NODE>>>(u, wu2t, bu2, hbuf,
                                                         NN, 384, 128);

    // finalize
    finalize_kernel<<<(NN * HD) / 256, 256>>>(out);
}

// round 5
// speedup vs baseline: 2.0835x; 1.0689x over previous
#include <cuda_runtime.h>
#include <math.h>
#include <stdint.h>

#define NN 32768
#define NE 524288
#define HD 128
#define ASW 36

__device__ __forceinline__ float ssilu(float v) {
    return v / ((1.0f + __expf(-v)) * 0.6f);
}
__device__ __forceinline__ float f2tf32(float x) {
    float r;
    asm("cvt.rna.tf32.f32 %0, %1;" : "=f"(r) : "f"(x));
    return r;
}
__device__ __forceinline__ float4 rnd4(float4 v) {
    v.x = f2tf32(v.x); v.y = f2tf32(v.y);
    v.z = f2tf32(v.z); v.w = f2tf32(v.w);
    return v;
}

// scratch ------------------------------------------------------------------
static __device__ float g_xln[NN * HD];
static __device__ float g_t1[NN * HD];
static __device__ float g_xh[NN * 3 * HD];
static __device__ float g_dx[NN * HD];
static __device__ float g_dvec[NN * 3 * HD];
static __device__ float g_xnew[NN * HD];
static __device__ float g_vecnew[NN * 3 * HD];
static __device__ float g_vecnewtf[NN * 3 * HD];
static __device__ float g_vproj[NN * 3 * 2 * HD];
static __device__ float g_vecdot[NN * HD];
static __device__ float g_cat[NN * 2 * HD];
static __device__ float g_u[NN * HD];
static __device__ float g_hbuf[NN * 3 * HD];
static __device__ float g_zerobias[512];
static __device__ float g_W1t[128 * 128];
static __device__ float g_W2t[128 * 384];
static __device__ float g_Wrt[64 * 384];
static __device__ float g_Wvt[128 * 256];
static __device__ float g_Wu1t[256 * 128];
static __device__ float g_Wu2t[128 * 384];

__constant__ float C_INV_SQRT_3 = 0.57735026918962576451f;
__constant__ float C_INV_SQRT_H = 0.08838834764831844055f;
__constant__ float C_INV_SQRT_2 = 0.70710678118654752440f;

// ---------------------------------------------------------------------------
__device__ __forceinline__ void cp16(float* s, const float* g) {
    uint32_t sa = (uint32_t)__cvta_generic_to_shared(s);
    asm volatile("cp.async.cg.shared.global [%0], [%1], 16;"
                 :: "r"(sa), "l"(g) : "memory");
}
__device__ __forceinline__ void mma8(float c[4], const uint32_t a[4],
                                     uint32_t b0, uint32_t b1) {
    asm volatile(
        "mma.sync.aligned.m16n8k8.row.col.f32.tf32.tf32.f32 "
        "{%0,%1,%2,%3}, {%4,%5,%6,%7}, {%8,%9}, {%0,%1,%2,%3};"
        : "+f"(c[0]), "+f"(c[1]), "+f"(c[2]), "+f"(c[3])
        : "r"(a[0]), "r"(a[1]), "r"(a[2]), "r"(a[3]), "r"(b0), "r"(b1));
}
__device__ __forceinline__ void red4(float* addr, float4 v) {
    asm volatile("red.global.add.v4.f32 [%0], {%1, %2, %3, %4};"
                 :: "l"(addr), "f"(v.x), "f"(v.y), "f"(v.z), "f"(v.w)
                 : "memory");
}

// ---------------------------------------------------------------------------
// Double-buffered tf32 MMA mainloop for the node GEMMs (inputs pre-rounded).
// ---------------------------------------------------------------------------
template <int BM, int BN>
__device__ __forceinline__ void mma_loop(
    const float* __restrict__ A, int lda,
    const float* __restrict__ B, int ldb, int K,
    float* sm, float acc[2][8][4]) {
    const int BSW = BN + 8;
    const int ABUF = BM * ASW;
    const int BBUF = 32 * BSW;
    float* As = sm;
    float* Bs = sm + 2 * ABUF;
    int tid = threadIdx.x;
    int wid = tid >> 5, lane = tid & 31;
    int g = lane >> 2, t = lane & 3;
    const int WN = BN / 64;
    int wm = wid / WN, wn = wid % WN;
    int mbase = wm * 32;

    {
#pragma unroll
        for (int i = 0; i < BM / 32; i++) {
            int f = tid + i * 256;
            int row = f >> 3, c4 = (f & 7) * 4;
            cp16(As + row * ASW + c4, A + (size_t)row * lda + c4);
        }
#pragma unroll
        for (int i = 0; i < BN / 32; i++) {
            int f = tid + i * 256;
            int row = f / (BN / 4), c4 = (f % (BN / 4)) * 4;
            cp16(Bs + row * BSW + c4, B + (size_t)row * ldb + c4);
        }
        asm volatile("cp.async.commit_group;" ::: "memory");
    }

    int nk = K >> 5;
    for (int kc = 0; kc < nk; kc++) {
        if (kc + 1 < nk) {
            int k0 = (kc + 1) * 32;
            float* as = As + ((kc + 1) & 1) * ABUF;
            float* bs = Bs + ((kc + 1) & 1) * BBUF;
#pragma unroll
            for (int i = 0; i < BM / 32; i++) {
                int f = tid + i * 256;
                int row = f >> 3, c4 = (f & 7) * 4;
                cp16(as + row * ASW + c4, A + (size_t)row * lda + k0 + c4);
            }
#pragma unroll
            for (int i = 0; i < BN / 32; i++) {
                int f = tid + i * 256;
                int row = f / (BN / 4), c4 = (f % (BN / 4)) * 4;
                cp16(bs + row * BSW + c4, B + (size_t)(k0 + row) * ldb + c4);
            }
            asm volatile("cp.async.commit_group;" ::: "memory");
            asm volatile("cp.async.wait_group 1;" ::: "memory");
        } else {
            asm volatile("cp.async.wait_group 0;" ::: "memory");
        }
        __syncthreads();
        const float* as = As + (kc & 1) * ABUF;
        const float* bs = Bs + (kc & 1) * BBUF;
#pragma unroll
        for (int ks = 0; ks < 4; ks++) {
            int kk = ks * 8;
            uint32_t af[2][4];
#pragma unroll
            for (int mt = 0; mt < 2; mt++) {
                int r0 = mbase + mt * 16;
                af[mt][0] = __float_as_uint(as[(r0 + g) * ASW + kk + t]);
                af[mt][1] = __float_as_uint(as[(r0 + g + 8) * ASW + kk + t]);
                af[mt][2] = __float_as_uint(as[(r0 + g) * ASW + kk + t + 4]);
                af[mt][3] = __float_as_uint(as[(r0 + g + 8) * ASW + kk + t + 4]);
            }
#pragma unroll
            for (int nt = 0; nt < 8; nt++) {
                int cb = wn * 64 + nt * 8;
                uint32_t b0 = __float_as_uint(bs[(kk + t) * BSW + cb + g]);
                uint32_t b1 = __float_as_uint(bs[(kk + t + 4) * BSW + cb + g]);
#pragma unroll
                for (int mt = 0; mt < 2; mt++) mma8(acc[mt][nt], af[mt], b0, b1);
            }
        }
        __syncthreads();
    }
}

// ---------------------------------------------------------------------------
// Single-stage edge mainloop: K=64 fully resident. A staged LDG->rna->STS,
// B staged via cp.async from pre-rounded weights. ESW=68 (conflict-free).
// ---------------------------------------------------------------------------
template <int BM, int BN>
__device__ __forceinline__ void edge_mma(
    const float* __restrict__ A,       // raw fp32, lda=64
    const float* __restrict__ B,       // pre-rounded, ldb=384
    float* sm, float acc[2][8][4]) {
    const int ESW = 68;
    const int BSW = BN + 8;
    float* As = sm;                    // BM * 68
    float* Bs = sm + BM * ESW;         // 64 * BSW
    int tid = threadIdx.x;

    // B: 64 rows x (BN/4) float4
#pragma unroll
    for (int i = 0; i < BN / 16; i++) {
        int f = tid + i * 256;
        int row = f / (BN / 4), c4 = (f % (BN / 4)) * 4;
        cp16(Bs + row * BSW + c4, B + (size_t)row * 384 + c4);
    }
    asm volatile("cp.async.commit_group;" ::: "memory");

    // A: BM rows x 16 float4, round to tf32 in flight
#pragma unroll
    for (int i = 0; i < BM / 16; i++) {
        int f = tid + i * 256;
        int row = f >> 4, c4 = (f & 15) * 4;
        float4 v = rnd4(*(const float4*)(A + (size_t)row * 64 + c4));
        *(float4*)(As + row * ESW + c4) = v;
    }
    asm volatile("cp.async.wait_group 0;" ::: "memory");
    __syncthreads();

    int wid = tid >> 5, lane = tid & 31;
    int g = lane >> 2, t = lane & 3;
    const int WN = BN / 64;
    int wm = wid / WN, wn = wid % WN;
    int mbase = wm * 32;
#pragma unroll
    for (int ks = 0; ks < 8; ks++) {
        int kk = ks * 8;
        uint32_t af[2][4];
#pragma unroll
        for (int mt = 0; mt < 2; mt++) {
            int r0 = mbase + mt * 16;
            af[mt][0] = __float_as_uint(As[(r0 + g) * ESW + kk + t]);
            af[mt][1] = __float_as_uint(As[(r0 + g + 8) * ESW + kk + t]);
            af[mt][2] = __float_as_uint(As[(r0 + g) * ESW + kk + t + 4]);
            af[mt][3] = __float_as_uint(As[(r0 + g + 8) * ESW + kk + t + 4]);
        }
#pragma unroll
        for (int nt = 0; nt < 8; nt++) {
            int cb = wn * 64 + nt * 8;
            uint32_t b0 = __float_as_uint(Bs[(kk + t) * BSW + cb + g]);
            uint32_t b1 = __float_as_uint(Bs[(kk + t + 4) * BSW + cb + g]);
#pragma unroll
            for (int mt = 0; mt < 2; mt++) mma8(acc[mt][nt], af[mt], b0, b1);
        }
    }
    __syncthreads();   // allow sm reuse as epilogue buffer
}

#define ACC_INIT(acc)                                   \
    _Pragma("unroll") for (int i = 0; i < 2; i++)       \
    _Pragma("unroll") for (int j = 0; j < 8; j++)       \
    _Pragma("unroll") for (int k = 0; k < 4; k++) acc[i][j][k] = 0.f;

// ---------------------------------------------------------------------------
// Node GEMM: C = act(A @ B + bias), 128x128 tile. RND rounds output to tf32.
// ---------------------------------------------------------------------------
template <int ACT, int RND>
__global__ void __launch_bounds__(256, 2)
gemm_tc(const float* __restrict__ A, const float* __restrict__ B,
        const float* __restrict__ bias, float* __restrict__ C,
        int M, int N, int K) {
    extern __shared__ float sm[];
    float acc[2][8][4];
    ACC_INIT(acc)
    int bm = blockIdx.y * 128;
    int bn = blockIdx.x * 128;
    mma_loop<128, 128>(A + (size_t)bm * K, K, B + bn, N, K, sm, acc);

    int tid = threadIdx.x;
    int wid = tid >> 5, lane = tid & 31;
    int g = lane >> 2, t = lane & 3;
    int wm = wid >> 1, wn = wid & 1;
#pragma unroll
    for (int mt = 0; mt < 2; mt++) {
#pragma unroll
        for (int h = 0; h < 2; h++) {
            int r = bm + wm * 32 + mt * 16 + g + h * 8;
#pragma unroll
            for (int nt = 0; nt < 8; nt++) {
                int c = bn + wn * 64 + nt * 8 + 2 * t;
                float2 bb = *(const float2*)(bias + c);
                float vx = acc[mt][nt][2 * h + 0] + bb.x;
                float vy = acc[mt][nt][2 * h + 1] + bb.y;
                if (ACT) { vx = ssilu(vx); vy = ssilu(vy); }
                if (RND) { vx = f2tf32(vx); vy = f2tf32(vy); }
                float2 o = {vx, vy};
                *(float2*)(C + (size_t)r * N + c) = o;
            }
        }
    }
}

// ---------------------------------------------------------------------------
// Edge kernel A: dx += xh1[src] * (ee @ Wr[:,0:128] + br[:128]); 128 edges/blk.
// ---------------------------------------------------------------------------
__global__ void __launch_bounds__(256, 2)
edge_gemm_dx(const float* __restrict__ ee, const float* __restrict__ br,
             const int* __restrict__ ei) {
    extern __shared__ float sm[];
    __shared__ int s_src[128];
    __shared__ int s_dst[128];
    int tid = threadIdx.x;
    int bm = blockIdx.x * 128;
    if (tid < 128) {
        s_src[tid] = ei[bm + tid];
        s_dst[tid] = ei[NE + bm + tid];
    }
    float acc[2][8][4];
    ACC_INIT(acc)
    edge_mma<128, 128>(ee + (size_t)bm * 64, g_Wrt, sm, acc);

    int wid = tid >> 5, lane = tid & 31;
    int g = lane >> 2, t = lane & 3;
    int wm = wid >> 1, wn = wid & 1;
    float* sbuf = sm;   // 128 x 132
#pragma unroll
    for (int mt = 0; mt < 2; mt++) {
#pragma unroll
        for (int h = 0; h < 2; h++) {
            int row = wm * 32 + mt * 16 + g + h * 8;
#pragma unroll
            for (int nt = 0; nt < 8; nt++) {
                int col = wn * 64 + nt * 8 + 2 * t;
                float2 bb = *(const float2*)(br + col);
                sbuf[row * 132 + col]     = acc[mt][nt][2 * h + 0] + bb.x;
                sbuf[row * 132 + col + 1] = acc[mt][nt][2 * h + 1] + bb.y;
            }
        }
    }
    __syncthreads();
#pragma unroll
    for (int i = 0; i < 16; i++) {
        int f = tid + i * 256;
        int e = f >> 5;
        int c4 = (f & 31) * 4;
        int src = s_src[e], dst = s_dst[e];
        float4 m = *(float4*)(sbuf + e * 132 + c4);
        float4 x1 = *(const float4*)(g_xh + (size_t)src * 384 + c4);
        m.x *= x1.x; m.y *= x1.y; m.z *= x1.z; m.w *= x1.w;
        red4(g_dx + (size_t)dst * HD + c4, m);
    }
}

// ---------------------------------------------------------------------------
// Edge kernel B: dvec scatter. 64 edges x 256 cols (rbf2 | rbf3).
// ---------------------------------------------------------------------------
__global__ void __launch_bounds__(256, 2)
edge_gemm_dvec(const float* __restrict__ ee, const float* __restrict__ br,
               const int* __restrict__ ei, const float* __restrict__ vec,
               const float* __restrict__ evec) {
    extern __shared__ float sm[];
    __shared__ int s_src[64];
    __shared__ int s_dst[64];
    __shared__ float s_ev[3][64];
    int tid = threadIdx.x;
    int bm = blockIdx.x * 64;
    if (tid < 64) {
        s_src[tid] = ei[bm + tid];
        s_dst[tid] = ei[NE + bm + tid];
    }
    if (tid < 192) {
        int e = tid & 63;
        int c = tid >> 6;
        s_ev[c][e] = evec[(size_t)(bm + e) * 3 + c];
    }
    float acc[2][8][4];
    ACC_INIT(acc)
    edge_mma<64, 256>(ee + (size_t)bm * 64, g_Wrt + 128, sm, acc);

    int wid = tid >> 5, lane = tid & 31;
    int g = lane >> 2, t = lane & 3;
    int wm = wid >> 2, wn = wid & 3;
    float* sbuf = sm;   // 64 x 260
#pragma unroll
    for (int mt = 0; mt < 2; mt++) {
#pragma unroll
        for (int h = 0; h < 2; h++) {
            int row = wm * 32 + mt * 16 + g + h * 8;
#pragma unroll
            for (int nt = 0; nt < 8; nt++) {
                int col = wn * 64 + nt * 8 + 2 * t;
                float2 bb = *(const float2*)(br + 128 + col);
                sbuf[row * 260 + col]     = acc[mt][nt][2 * h + 0] + bb.x;
                sbuf[row * 260 + col + 1] = acc[mt][nt][2 * h + 1] + bb.y;
            }
        }
    }
    __syncthreads();
#pragma unroll
    for (int i = 0; i < 8; i++) {
        int f = tid + i * 256;
        int e = f >> 5;
        int c4 = (f & 31) * 4;
        int src = s_src[e], dst = s_dst[e];
        float ev0 = s_ev[0][e], ev1 = s_ev[1][e], ev2 = s_ev[2][e];
        float4 r2 = *(float4*)(sbuf + e * 260 + c4);
        float4 r3 = *(float4*)(sbuf + e * 260 + 128 + c4);
        const float* xhp = g_xh + (size_t)src * 384;
        float4 x2 = *(const float4*)(xhp + 128 + c4);
        float4 x3 = *(const float4*)(xhp + 256 + c4);
        float4 m2, m3;
        m2.x = r2.x * x2.x * C_INV_SQRT_3; m2.y = r2.y * x2.y * C_INV_SQRT_3;
        m2.z = r2.z * x2.z * C_INV_SQRT_3; m2.w = r2.w * x2.w * C_INV_SQRT_3;
        m3.x = r3.x * x3.x; m3.y = r3.y * x3.y;
        m3.z = r3.z * x3.z; m3.w = r3.w * x3.w;
        const float* vp = vec + (size_t)src * 384;
        float* dvp = g_dvec + (size_t)dst * 384;
#pragma unroll
        for (int c = 0; c < 3; c++) {
            float ev = (c == 0) ? ev0 : ((c == 1) ? ev1 : ev2);
            float4 vv = *(const float4*)(vp + c * 128 + c4);
            float4 msg;
            msg.x = (vv.x * m2.x + m3.x * ev) * C_INV_SQRT_H;
            msg.y = (vv.y * m2.y + m3.y * ev) * C_INV_SQRT_H;
            msg.z = (vv.z * m2.z + m3.z * ev) * C_INV_SQRT_H;
            msg.w = (vv.w * m2.w + m3.w * ev) * C_INV_SQRT_H;
            red4(dvp + c * 128 + c4, msg);
        }
    }
}

// ---------------------------------------------------------------------------
__global__ void zero_acc_kernel() {
    int total4 = (NN * HD + NN * 3 * HD) / 4;
    float4 z = make_float4(0.f, 0.f, 0.f, 0.f);
    for (int i = blockIdx.x * blockDim.x + threadIdx.x; i < total4;
         i += gridDim.x * blockDim.x) {
        if (i < NN * HD / 4)
            ((float4*)g_dx)[i] = z;
        else
            ((float4*)g_dvec)[i - NN * HD / 4] = z;
    }
}

// round all weights -> tf32 copies -------------------------------------------
__global__ void round_w_kernel(const float* __restrict__ W1,
                               const float* __restrict__ W2,
                               const float* __restrict__ Wr,
                               const float* __restrict__ Wv,
                               const float* __restrict__ Wu1,
                               const float* __restrict__ Wu2) {
    const int s1 = 128 * 128 / 4, s2 = 128 * 384 / 4, s3 = 64 * 384 / 4;
    const int s4 = 128 * 256 / 4, s5 = 256 * 128 / 4, s6 = 128 * 384 / 4;
    int i = blockIdx.x * blockDim.x + threadIdx.x;
    int stride = gridDim.x * blockDim.x;
    for (; i < s1 + s2 + s3 + s4 + s5 + s6; i += stride) {
        int j = i;
        if (j < s1) { ((float4*)g_W1t)[j] = rnd4(((const float4*)W1)[j]); continue; }
        j -= s1;
        if (j < s2) { ((float4*)g_W2t)[j] = rnd4(((const float4*)W2)[j]); continue; }
        j -= s2;
        if (j < s3) { ((float4*)g_Wrt)[j] = rnd4(((const float4*)Wr)[j]); continue; }
        j -= s3;
        if (j < s4) { ((float4*)g_Wvt)[j] = rnd4(((const float4*)Wv)[j]); continue; }
        j -= s4;
        if (j < s5) { ((float4*)g_Wu1t)[j] = rnd4(((const float4*)Wu1)[j]); continue; }
        j -= s5;
        ((float4*)g_Wu2t)[j] = rnd4(((const float4*)Wu2)[j]);
    }
}

// ---------------------------------------------------------------------------
__global__ void ln_kernel(const float* __restrict__ x,
                          const float* __restrict__ g,
                          const float* __restrict__ b) {
    int row = blockIdx.x * (blockDim.x >> 5) + (threadIdx.x >> 5);
    int lane = threadIdx.x & 31;
    if (row >= NN) return;
    float4 v = *(const float4*)(x + (size_t)row * HD + lane * 4);
    float s = v.x + v.y + v.z + v.w;
    float s2 = v.x * v.x + v.y * v.y + v.z * v.z + v.w * v.w;
#pragma unroll
    for (int o = 16; o > 0; o >>= 1) {
        s += __shfl_xor_sync(0xffffffffu, s, o);
        s2 += __shfl_xor_sync(0xffffffffu, s2, o);
    }
    float mu = s * (1.0f / HD);
    float var = s2 * (1.0f / HD) - mu * mu;
    float inv = rsqrtf(var + 1e-5f);
    float4 gg = *(const float4*)(g + lane * 4);
    float4 bb = *(const float4*)(b + lane * 4);
    float4 o4;
    o4.x = f2tf32((v.x - mu) * inv * gg.x + bb.x);
    o4.y = f2tf32((v.y - mu) * inv * gg.y + bb.y);
    o4.z = f2tf32((v.z - mu) * inv * gg.z + bb.z);
    o4.w = f2tf32((v.w - mu) * inv * gg.w + bb.w);
    *(float4*)(g_xln + (size_t)row * HD + lane * 4) = o4;
}

// ---------------------------------------------------------------------------
__global__ void node_mid_kernel(const float* __restrict__ x,
                                const float* __restrict__ vec) {
    int i = blockIdx.x * blockDim.x + threadIdx.x;
    if (i < NN * 3 * HD) {
        float vn = vec[i] + g_dvec[i];
        g_vecnew[i] = vn;
        g_vecnewtf[i] = f2tf32(vn);
    }
    if (i < NN * HD) g_xnew[i] = (x[i] + g_dx[i]) * C_INV_SQRT_2;
}

// ---------------------------------------------------------------------------
__global__ void dotnorm_kernel() {
    int i = blockIdx.x * blockDim.x + threadIdx.x;
    if (i >= NN * HD) return;
    int n = i >> 7;
    int h = i & 127;
    const float* vp = g_vproj + (size_t)n * 768;
    float d = 0.f, s = 0.f;
#pragma unroll
    for (int c = 0; c < 3; c++) {
        float v1 = vp[c * 256 + h];
        float v2 = vp[c * 256 + 128 + h];
        d += v1 * v2;
        s += v2 * v2;
    }
    g_vecdot[i] = d * C_INV_SQRT_H;
    g_cat[(size_t)n * 256 + h] = f2tf32(g_xnew[i]);
    g_cat[(size_t)n * 256 + 128 + h] = f2tf32(sqrtf(s + 1e-8f));
}

// ---------------------------------------------------------------------------
__global__ void finalize_kernel(float* __restrict__ out) {
    int i = blockIdx.x * blockDim.x + threadIdx.x;
    if (i >= NN * HD) return;
    int n = i >> 7;
    int h = i & 127;
    const float* hb = g_hbuf + (size_t)n * 384;
    float xv1 = hb[h];
    float xv2 = hb[128 + h];
    float xv3 = hb[256 + h];
    float* out_vec = out;
    float* out_x = out + (size_t)NN * 3 * HD;
    out_x[i] = g_xnew[i] + (xv1 + xv2 * g_vecdot[i]) * C_INV_SQRT_2;
#pragma unroll
    for (int c = 0; c < 3; c++) {
        size_t idx = (size_t)n * 384 + c * HD + h;
        out_vec[idx] = g_vecnew[idx] + xv3 * g_vproj[(size_t)n * 768 + c * 256 + h];
    }
}

// ---------------------------------------------------------------------------
extern "C" void kernel_launch(void* const* d_in, const int* in_sizes, int n_in,
                              void* d_out, int out_size) {
    const float* x    = (const float*)d_in[0];
    const float* vec  = (const float*)d_in[1];
    const int*   ei   = (const int*)d_in[2];
    const float* ee   = (const float*)d_in[3];
    const float* evec = (const float*)d_in[4];
    const float* ln_g = (const float*)d_in[5];
    const float* ln_b = (const float*)d_in[6];
    const float* W1   = (const float*)d_in[7];
    const float* b1   = (const float*)d_in[8];
    const float* W2   = (const float*)d_in[9];
    const float* b2   = (const float*)d_in[10];
    const float* Wr   = (const float*)d_in[11];
    const float* br   = (const float*)d_in[12];
    const float* Wv   = (const float*)d_in[13];
    const float* Wu1  = (const float*)d_in[14];
    const float* bu1  = (const float*)d_in[15];
    const float* Wu2  = (const float*)d_in[16];
    const float* bu2  = (const float*)d_in[17];

    float* out = (float*)d_out;

    float* zb = nullptr;      cudaGetSymbolAddress((void**)&zb, g_zerobias);
    float* xln = nullptr;     cudaGetSymbolAddress((void**)&xln, g_xln);
    float* t1 = nullptr;      cudaGetSymbolAddress((void**)&t1, g_t1);
    float* vecnewtf = nullptr; cudaGetSymbolAddress((void**)&vecnewtf, g_vecnewtf);
    float* vproj = nullptr;   cudaGetSymbolAddress((void**)&vproj, g_vproj);
    float* cat = nullptr;     cudaGetSymbolAddress((void**)&cat, g_cat);
    float* u = nullptr;       cudaGetSymbolAddress((void**)&u, g_u);
    float* hbuf = nullptr;    cudaGetSymbolAddress((void**)&hbuf, g_hbuf);
    float* xh = nullptr;      cudaGetSymbolAddress((void**)&xh, g_xh);
    float* w1t = nullptr;     cudaGetSymbolAddress((void**)&w1t, g_W1t);
    float* w2t = nullptr;     cudaGetSymbolAddress((void**)&w2t, g_W2t);
    float* wvt = nullptr;     cudaGetSymbolAddress((void**)&wvt, g_Wvt);
    float* wu1t = nullptr;    cudaGetSymbolAddress((void**)&wu1t, g_Wu1t);
    float* wu2t = nullptr;    cudaGetSymbolAddress((void**)&wu2t, g_Wu2t);

    const int SMEM_NODE = (2 * 128 * ASW + 2 * 32 * 136) * 4;         // 71680
    const int SMEM_EDX  = (128 * 68 + 64 * 136) * 4;                  // 69632
    const int SMEM_EDV  = (64 * 68 + 64 * 264) * 4;                   // 84992

    cudaFuncSetAttribute((const void*)gemm_tc<0, 0>,
                         cudaFuncAttributeMaxDynamicSharedMemorySize, SMEM_NODE);
    cudaFuncSetAttribute((const void*)gemm_tc<1, 1>,
                         cudaFuncAttributeMaxDynamicSharedMemorySize, SMEM_NODE);
    cudaFuncSetAttribute((const void*)edge_gemm_dx,
                         cudaFuncAttributeMaxDynamicSharedMemorySize, SMEM_EDX);
    cudaFuncSetAttribute((const void*)edge_gemm_dvec,
                         cudaFuncAttributeMaxDynamicSharedMemorySize, SMEM_EDV);

    // prep
    zero_acc_kernel<<<2048, 256>>>();
    round_w_kernel<<<256, 256>>>(W1, W2, Wr, Wv, Wu1, Wu2);

    // LayerNorm (tf32-rounded output)
    ln_kernel<<<NN / 8, 256>>>(x, ln_g, ln_b);

    // t1 = rna(scaled_silu(xln @ W1 + b1))
    gemm_tc<1, 1><<<dim3(1, NN / 128), 256, SMEM_NODE>>>(xln, w1t, b1, t1,
                                                         NN, 128, 128);
    // xh = t1 @ W2 + b2
    gemm_tc<0, 0><<<dim3(3, NN / 128), 256, SMEM_NODE>>>(t1, w2t, b2, xh,
                                                         NN, 384, 128);

    // fused rbfh GEMM + message + scatter (raw ee, rna at staging)
    edge_gemm_dx<<<NE / 128, 256, SMEM_EDX>>>(ee, br, ei);
    edge_gemm_dvec<<<NE / 64, 256, SMEM_EDV>>>(ee, br, ei, vec, evec);

    // x_new, vec_new
    node_mid_kernel<<<(NN * 3 * HD + 255) / 256, 256>>>(x, vec);

    // vproj = vec_new @ Wv
    gemm_tc<0, 0><<<dim3(2, (3 * NN) / 128), 256, SMEM_NODE>>>(
        vecnewtf, wvt, zb, vproj, 3 * NN, 256, 128);

    // vec_dot / vec2_norm / cat
    dotnorm_kernel<<<(NN * HD) / 256, 256>>>();

    // u = rna(scaled_silu(cat @ Wu1 + bu1))
    gemm_tc<1, 1><<<dim3(1, NN / 128), 256, SMEM_NODE>>>(cat, wu1t, bu1, u,
                                                         NN, 128, 256);
    // hbuf = u @ Wu2 + bu2
    gemm_tc<0, 0><<<dim3(3, NN / 128), 256, SMEM_NODE>>>(u, wu2t, bu2, hbuf,
                                                         NN, 384, 128);

    // finalize
    finalize_kernel<<<(NN * HD) / 256, 256>>>(out);
}